// round 10
// baseline (speedup 1.0000x reference)
#include <cuda_runtime.h>
#include <cuda_bf16.h>
#include <math.h>
#include <stdint.h>

#define BATCH 32

// ---------------- persistent scratch (device globals; no allocation) ----------------
__device__ float g_gray[BATCH*10000];
__device__ float g_d1 [BATCH*691200];          // rgb distances  (B,75,96,96)
__device__ float g_d1g[BATCH*230400];          // gray distances (B,25,96,96)
__device__ float g_act2[BATCH*230400];         // after triangle+sfm (B,100,48,48)
__device__ float g_act3[BATCH*129600];         // after triangle+sfm (B,225,24,24)
__device__ float g_d2 [BATCH*518400];          // conv1 distances (B,225,48,48)
__device__ float g_d3 [BATCH*302500];          // conv2 distances (B,625,22,22)

// bf16 hi/lo split operands (padded; conv2 M padded 15488->15616 for 256-row tiles)
__device__ __align__(16) __nv_bfloat16 g_col1h[73728*960];
__device__ __align__(16) __nv_bfloat16 g_col1l[73728*960];
__device__ __align__(16) __nv_bfloat16 g_col2h[15616*2048];
__device__ __align__(16) __nv_bfloat16 g_col2l[15616*2048];
__device__ __align__(16) __nv_bfloat16 g_w1h[256*960];
__device__ __align__(16) __nv_bfloat16 g_w1l[256*960];
__device__ __align__(16) __nv_bfloat16 g_w2h[640*2048];
__device__ __align__(16) __nv_bfloat16 g_w2l[640*2048];
__device__ float g_s2a [73728];
__device__ float g_s2b [15616];
__device__ float g_wsq1[256];
__device__ float g_wsq2[640];

__device__ unsigned g_histo[64*2048];      // filtered-pass histos (zero-invariant); 64 slots for merged stage-1
__device__ unsigned g_h1a[BATCH*2048];     // pass-1 histo (producer-filled) A
__device__ unsigned g_h1b[BATCH*2048];     // pass-1 histo (producer-filled) B
__device__ unsigned g_prefix[64];
__device__ int      g_krem[64];
__device__ float    g_thrA[BATCH];
__device__ float    g_thrB[BATCH];

#define FC_CHUNKS 8
__device__ float g_fcpart[FC_CHUNKS*BATCH*10];

// ---------------- ptx helpers (plain sm_103-safe: no tcgen05) ----------------
__device__ __forceinline__ uint32_t smem_u32(const void* p) {
    uint32_t a;
    asm("{ .reg .u64 t; cvta.to.shared.u64 t, %1; cvt.u32.u64 %0, t; }" : "=r"(a) : "l"(p));
    return a;
}
__device__ __forceinline__ void cp16(uint32_t dst, const void* src) {
    asm volatile("cp.async.cg.shared.global [%0], [%1], 16;" :: "r"(dst), "l"(src));
}
#define CP_COMMIT() asm volatile("cp.async.commit_group;" ::: "memory")
#define CP_WAIT1()  asm volatile("cp.async.wait_group 1;" ::: "memory")
#define CP_WAIT0()  asm volatile("cp.async.wait_group 0;" ::: "memory")

__device__ __forceinline__ void ldm_x4(uint32_t* r, uint32_t addr) {
    asm volatile("ldmatrix.sync.aligned.m8n8.x4.shared.b16 {%0,%1,%2,%3}, [%4];"
                 : "=r"(r[0]), "=r"(r[1]), "=r"(r[2]), "=r"(r[3]) : "r"(addr));
}
__device__ __forceinline__ void mma_bf16(float* d, const uint32_t* a, const uint32_t* b) {
    asm volatile("mma.sync.aligned.m16n8k16.row.col.f32.bf16.bf16.f32 "
                 "{%0,%1,%2,%3}, {%4,%5,%6,%7}, {%8,%9}, {%0,%1,%2,%3};"
                 : "+f"(d[0]), "+f"(d[1]), "+f"(d[2]), "+f"(d[3])
                 : "r"(a[0]), "r"(a[1]), "r"(a[2]), "r"(a[3]), "r"(b[0]), "r"(b[1]));
}
#define SWZ128(x) ((x) ^ (((x) >> 3) & 0x70))

__device__ __forceinline__ float tri_val(float v, float thr, float invw) {
    return (v > thr) ? 0.0f : 1.0f - v * invw;
}

// warp-aggregated histogram add (concentrated distributions -> ~32x fewer atomics)
__device__ __forceinline__ void hist_add(unsigned* sh, unsigned key) {
    unsigned am = __activemask();
    unsigned mk = __match_any_sync(am, key);
    int leader = __ffs(mk) - 1;
    if ((int)(threadIdx.x & 31) == leader) atomicAdd(&sh[key], (unsigned)__popc(mk));
}

// ---------------- parallel k-th-bin search (256-thread block) ----------------
__device__ __forceinline__ unsigned block_kth(const unsigned* hist, int nbins, unsigned k,
                                              unsigned* scanbuf, int* sel_sm, unsigned* krem_sm,
                                              int tid) {
    int per = nbins >> 8;
    int base = tid * per;
    unsigned own = 0;
    for (int j = 0; j < per; j++) own += hist[base + j];
    scanbuf[tid] = own;
    __syncthreads();
    for (int off = 1; off < 256; off <<= 1) {
        unsigned v = (tid >= off) ? scanbuf[tid - off] : 0u;
        __syncthreads();
        scanbuf[tid] += v;
        __syncthreads();
    }
    unsigned incl = scanbuf[tid];
    unsigned excl = incl - own;
    if (excl < k && incl >= k) {
        unsigned c = excl;
        for (int j = 0; j < per; j++) {
            unsigned v = hist[base + j];
            if (c + v >= k) { *sel_sm = base + j; *krem_sm = k - c; break; }
            c += v;
        }
    }
    __syncthreads();
    return (unsigned)*sel_sm;
}

// ---------------- grayscale ----------------
__global__ void k_gray(const float* __restrict__ x) {
    int i = blockIdx.x * blockDim.x + threadIdx.x;
    if (i >= BATCH*10000) return;
    int b = i / 10000, p = i - b*10000;
    const float* xb = x + (size_t)b * 30000;
    g_gray[i] = 0.2989f*xb[p] + 0.587f*xb[10000+p] + 0.114f*xb[20000+p];
}

// ---------------- rgb conv (5x5) -> d1, with fused pass-1 histogram ----------------
__global__ void k_rgbconv(const float* __restrict__ x, const float* __restrict__ rgb_w) {
    __shared__ float sw[225];
    __shared__ float swsq[75];
    __shared__ unsigned hist[2048];
    int t = threadIdx.x;
    if (t < 225) sw[t] = rgb_w[t];
    for (int j = t; j < 2048; j += 256) hist[j] = 0u;
    __syncthreads();
    if (t < 75) {
        float a = sw[t*3], b2 = sw[t*3+1], c = sw[t*3+2];
        swsq[t] = a*a + b2*b2 + c*c;
    }
    __syncthreads();
    int i = blockIdx.x * 256 + t;
    int b = i / 9216, l = i - b*9216;
    int oy = l / 96, ox = l - oy*96;
    const float* xb = x + (size_t)b * 30000;
    float s1[3];
    float s2 = 0.f;
    #pragma unroll
    for (int c = 0; c < 3; c++) {
        float sc = 0.f;
        const float* xc = xb + c*10000;
        #pragma unroll
        for (int dy = 0; dy < 5; dy++) {
            const float* row = xc + (oy+dy)*100 + ox;
            #pragma unroll
            for (int dx = 0; dx < 5; dx++) { float v = row[dx]; sc += v; s2 += v*v; }
        }
        s1[c] = sc;
    }
    float* o = g_d1 + (size_t)b * 691200 + l;
    #pragma unroll 5
    for (int f = 0; f < 75; f++) {
        float d2 = s2 + 25.0f*swsq[f]
                 - 2.0f*(sw[f*3]*s1[0] + sw[f*3+1]*s1[1] + sw[f*3+2]*s1[2]);
        float d = sqrtf(fmaxf(d2, 0.0f));
        o[(size_t)f*9216] = d;
        hist_add(hist, __float_as_uint(d) >> 21);
    }
    __syncthreads();
    int bb = blockIdx.x / 36;
    for (int j = t; j < 2048; j += 256)
        if (hist[j]) atomicAdd(&g_h1a[bb*2048 + j], hist[j]);
}

// ---------------- gray RBF conv (5x5) -> d1g, with fused pass-1 histogram ----------------
__global__ void k_grayconv(const float* __restrict__ gray_w) {
    __shared__ float sw[625];
    __shared__ float swsq[25];
    __shared__ unsigned hist[2048];
    int t = threadIdx.x;
    for (int j = t; j < 625; j += 256) sw[j] = gray_w[j];
    for (int j = t; j < 2048; j += 256) hist[j] = 0u;
    __syncthreads();
    if (t < 25) {
        float s = 0.f;
        for (int k = 0; k < 25; k++) { float v = sw[t*25+k]; s += v*v; }
        swsq[t] = s;
    }
    __syncthreads();
    int i = blockIdx.x * 256 + t;
    int b = i / 9216, l = i - b*9216;
    int oy = l / 96, ox = l - oy*96;
    const float* gb = g_gray + (size_t)b * 10000;
    float p[25];
    float pn = 0.f;
    #pragma unroll
    for (int dy = 0; dy < 5; dy++) {
        const float* row = gb + (oy+dy)*100 + ox;
        #pragma unroll
        for (int dx = 0; dx < 5; dx++) { float v = row[dx]; p[dy*5+dx] = v; pn += v*v; }
    }
    float* o = g_d1g + (size_t)b * 230400 + l;
    #pragma unroll 5
    for (int f = 0; f < 25; f++) {
        float dot = 0.f;
        #pragma unroll
        for (int k = 0; k < 25; k++) dot += sw[f*25+k] * p[k];
        float d = sqrtf(fmaxf(pn + swsq[f] - 2.0f*dot, 0.0f));
        o[(size_t)f*9216] = d;
        hist_add(hist, __float_as_uint(d) >> 21);
    }
    __syncthreads();
    int bb = blockIdx.x / 36;
    for (int j = t; j < 2048; j += 256)
        if (hist[j]) atomicAdd(&g_h1b[bb*2048 + j], hist[j]);
}

// ---------------- single-select kernels (slots 0..31) ----------------
__global__ void k_scan1p(unsigned* __restrict__ h1, int kk) {
    __shared__ unsigned scanbuf[256];
    __shared__ int ssel;
    __shared__ unsigned skrem;
    int b = blockIdx.x, tid = threadIdx.x;
    unsigned* h = h1 + b*2048;
    unsigned sel = block_kth(h, 2048, (unsigned)kk, scanbuf, &ssel, &skrem, tid);
    if (tid == 0) { g_prefix[b] = sel << 21; g_krem[b] = (int)skrem; }
    __syncthreads();
    for (int j = tid; j < 2048; j += 256) h[j] = 0u;
}

__global__ void k_hist(const float* __restrict__ data, int Nper, int shift, int nbins, int hichk) {
    __shared__ unsigned sh[2048];
    int t = threadIdx.x;
    for (int j = t; j < nbins; j += blockDim.x) sh[j] = 0u;
    __syncthreads();
    int b = blockIdx.y;
    unsigned want = g_prefix[b] >> hichk;
    const uint4* p = (const uint4*)(data + (size_t)b * Nper);
    unsigned mask = (unsigned)nbins - 1u;
    int n4 = Nper >> 2;
    for (int i = blockIdx.x * blockDim.x + t; i < n4; i += gridDim.x * blockDim.x) {
        uint4 u = p[i];
        if ((u.x >> hichk) == want) atomicAdd(&sh[(u.x >> shift) & mask], 1u);
        if ((u.y >> hichk) == want) atomicAdd(&sh[(u.y >> shift) & mask], 1u);
        if ((u.z >> hichk) == want) atomicAdd(&sh[(u.z >> shift) & mask], 1u);
        if ((u.w >> hichk) == want) atomicAdd(&sh[(u.w >> shift) & mask], 1u);
    }
    __syncthreads();
    for (int j = t; j < nbins; j += blockDim.x)
        if (sh[j]) atomicAdd(&g_histo[b*2048+j], sh[j]);
}

__global__ void k_scanp(int nbins, int shift, int finalize, const float* wptr, float* thrOut) {
    __shared__ unsigned scanbuf[256];
    __shared__ int ssel;
    __shared__ unsigned skrem;
    int b = blockIdx.x, tid = threadIdx.x;
    unsigned* h = &g_histo[b*2048];
    unsigned sel = block_kth(h, nbins, (unsigned)g_krem[b], scanbuf, &ssel, &skrem, tid);
    if (tid == 0) {
        g_prefix[b] |= sel << shift;
        g_krem[b] = (int)skrem;
        if (finalize) thrOut[b] = fminf(__uint_as_float(g_prefix[b]), wptr[0]);
    }
    __syncthreads();
    for (int j = tid; j < 2048; j += 256) h[j] = 0u;
}

// ---------------- merged stage-1 selects (slots 0..31 = A, 32..63 = B) ----------------
__global__ void k_scan1m(int kkA, int kkB) {
    __shared__ unsigned scanbuf[256];
    __shared__ int ssel;
    __shared__ unsigned skrem;
    int b = blockIdx.x, tid = threadIdx.x;
    unsigned* h = (b < 32) ? &g_h1a[b*2048] : &g_h1b[(b-32)*2048];
    unsigned kk = (b < 32) ? (unsigned)kkA : (unsigned)kkB;
    unsigned sel = block_kth(h, 2048, kk, scanbuf, &ssel, &skrem, tid);
    if (tid == 0) { g_prefix[b] = sel << 21; g_krem[b] = (int)skrem; }
    __syncthreads();
    for (int j = tid; j < 2048; j += 256) h[j] = 0u;
}

__global__ void k_histm(const float* __restrict__ dA, const float* __restrict__ dB,
                        int shift, int nbins, int hichk) {
    __shared__ unsigned sh[2048];
    int t = threadIdx.x;
    for (int j = t; j < nbins; j += blockDim.x) sh[j] = 0u;
    __syncthreads();
    int yy = blockIdx.y;
    bool isA = yy < 32;
    int b = isA ? yy : yy - 32;
    int Nper = isA ? 691200 : 230400;
    const uint4* p = (const uint4*)((isA ? dA + (size_t)b*691200 : dB + (size_t)b*230400));
    unsigned want = g_prefix[yy] >> hichk;
    unsigned mask = (unsigned)nbins - 1u;
    int n4 = Nper >> 2;
    for (int i = blockIdx.x * blockDim.x + t; i < n4; i += gridDim.x * blockDim.x) {
        uint4 u = p[i];
        if ((u.x >> hichk) == want) atomicAdd(&sh[(u.x >> shift) & mask], 1u);
        if ((u.y >> hichk) == want) atomicAdd(&sh[(u.y >> shift) & mask], 1u);
        if ((u.z >> hichk) == want) atomicAdd(&sh[(u.z >> shift) & mask], 1u);
        if ((u.w >> hichk) == want) atomicAdd(&sh[(u.w >> shift) & mask], 1u);
    }
    __syncthreads();
    for (int j = t; j < nbins; j += blockDim.x)
        if (sh[j]) atomicAdd(&g_histo[yy*2048+j], sh[j]);
}

__global__ void k_scanm(int nbins, int shift, int finalize, const float* wptr) {
    __shared__ unsigned scanbuf[256];
    __shared__ int ssel;
    __shared__ unsigned skrem;
    int b = blockIdx.x, tid = threadIdx.x;
    unsigned* h = &g_histo[b*2048];
    unsigned sel = block_kth(h, nbins, (unsigned)g_krem[b], scanbuf, &ssel, &skrem, tid);
    if (tid == 0) {
        g_prefix[b] |= sel << shift;
        g_krem[b] = (int)skrem;
        if (finalize) {
            float thr = fminf(__uint_as_float(g_prefix[b]), wptr[0]);
            if (b < 32) g_thrA[b] = thr; else g_thrB[b-32] = thr;
        }
    }
    __syncthreads();
    for (int j = tid; j < 2048; j += 256) h[j] = 0u;
}

// ---------------- fused triangle + sfm (stage 1) ----------------
__global__ void k_sfm1(const float* __restrict__ w1) {
    int i = blockIdx.x * blockDim.x + threadIdx.x;
    if (i >= BATCH*230400) return;
    int b = i / 230400;
    int r = i - b*230400;
    int c = r / 2304;
    int l = r - c*2304;
    int oy = l / 48, ox = l - oy*48;
    float thr;
    const float* src;
    if (c < 75) { thr = g_thrA[b]; src = g_d1  + (size_t)b*691200 + (size_t)c*9216; }
    else        { thr = g_thrB[b]; src = g_d1g + (size_t)b*230400 + (size_t)(c-75)*9216; }
    float invw = 1.0f / w1[0];
    int y = 2*oy, x2 = 2*ox;
    float v00 = tri_val(src[y*96 + x2],       thr, invw);
    float v01 = tri_val(src[y*96 + x2 + 1],   thr, invw);
    float v10 = tri_val(src[(y+1)*96 + x2],   thr, invw);
    float v11 = tri_val(src[(y+1)*96 + x2+1], thr, invw);
    g_act2[i] = 0.25f * (0.90f*v00 + 0.93f*v01 + 0.96f*v10 + 0.99f*v11);
}

// ---------------- fused triangle + sfm (stage 2) ----------------
__global__ void k_sfm2(const float* __restrict__ w2) {
    int i = blockIdx.x * blockDim.x + threadIdx.x;
    if (i >= BATCH*129600) return;
    int b = i / 129600;
    int r = i - b*129600;
    int c = r / 576;
    int l = r - c*576;
    int oy = l / 24, ox = l - oy*24;
    float thr = g_thrA[b];
    float invw = 1.0f / w2[0];
    const float* src = g_d2 + ((size_t)b*225 + c) * 2304;
    int y = 2*oy, x2 = 2*ox;
    float v00 = tri_val(src[y*48 + x2],       thr, invw);
    float v01 = tri_val(src[y*48 + x2 + 1],   thr, invw);
    float v10 = tri_val(src[(y+1)*48 + x2],   thr, invw);
    float v11 = tri_val(src[(y+1)*48 + x2+1], thr, invw);
    g_act3[i] = 0.25f * (0.90f*v00 + 0.93f*v01 + 0.96f*v10 + 0.99f*v11);
}

// ---------------- staged-smem im2col -> bf16 hi/lo + row s2 ----------------
__global__ void __launch_bounds__(256) k_im2col_stage(
    const float* __restrict__ in,
    __nv_bfloat16* __restrict__ outh, __nv_bfloat16* __restrict__ outl,
    float* __restrict__ s2out,
    int C, int Hin, int Win, int oh, int ow, int pad, int Ktrue, int Kpad)
{
    extern __shared__ char smraw[];
    float* sm = (float*)smraw;
    int W2 = Win + 2*pad;
    int stageN = C * 3 * W2;
    int* kcol = (int*)(smraw + (size_t)stageN * 4);

    int bid = blockIdx.x;
    int b = bid / oh, oy = bid - b*oh;
    int tid = threadIdx.x;

    for (int k = tid; k < Ktrue; k += 256) {
        int c = k / 9; int r = k - c*9; int di = r / 3; int dj = r - di*3;
        kcol[k] = (c*3 + di)*W2 + dj;
    }
    const float* inb = in + (size_t)b * C * Hin * Win;
    for (int idx = tid; idx < stageN; idx += 256) {
        int c = idx / (3*W2); int rem = idx - c*3*W2;
        int dy = rem / W2; int xx = rem - dy*W2;
        int iy = oy + dy - pad; int ix = xx - pad;
        float v = 0.f;
        if (iy >= 0 && iy < Hin && ix >= 0 && ix < Win)
            v = inb[((size_t)c*Hin + iy)*Win + ix];
        sm[idx] = v;
    }
    __syncthreads();

    int L = oh * ow;
    int mbase = b*L + oy*ow;
    int KH = Kpad >> 1;
    int total = ow * KH;
    int ox = tid / KH, p = tid - ox*KH;
    for (int j = tid; j < total; j += 256) {
        int k0 = p*2, k1 = k0 + 1;
        float v0 = (k0 < Ktrue) ? sm[kcol[k0] + ox] : 0.f;
        float v1 = (k1 < Ktrue) ? sm[kcol[k1] + ox] : 0.f;
        __nv_bfloat16 h0 = __float2bfloat16(v0);
        __nv_bfloat16 h1 = __float2bfloat16(v1);
        __nv_bfloat16 l0 = __float2bfloat16(v0 - __bfloat162float(h0));
        __nv_bfloat16 l1 = __float2bfloat16(v1 - __bfloat162float(h1));
        size_t off = (size_t)(mbase + ox) * Kpad + k0;
        *(__nv_bfloat162*)(outh + off) = __nv_bfloat162(h0, h1);
        *(__nv_bfloat162*)(outl + off) = __nv_bfloat162(l0, l1);
        p += 256;
        if (p >= KH) { p -= KH; ox++; }
    }

    int wid = tid >> 5, lane = tid & 31;
    for (int oxx = wid; oxx < ow; oxx += 8) {
        float s = 0.f;
        for (int k = lane; k < Ktrue; k += 32) {
            float v = sm[kcol[k] + oxx];
            __nv_bfloat16 h = __float2bfloat16(v);
            float fh = __bfloat162float(h);
            __nv_bfloat16 lo = __float2bfloat16(v - fh);
            float rec = fh + __bfloat162float(lo);
            s += rec*rec;
        }
        #pragma unroll
        for (int o2 = 16; o2 > 0; o2 >>= 1) s += __shfl_down_sync(0xFFFFFFFFu, s, o2);
        if (lane == 0) s2out[mbase + oxx] = s;
    }
}

// ---------------- weight prep: pad + bf16 split ----------------
__global__ void k_wprep(const float* __restrict__ w,
                        __nv_bfloat16* __restrict__ outh, __nv_bfloat16* __restrict__ outl,
                        int N, int K, int Npad, int Kpad) {
    int i = blockIdx.x * blockDim.x + threadIdx.x;
    if (i >= Npad*Kpad) return;
    int n = i / Kpad, k = i - n*Kpad;
    float v = (n < N && k < K) ? w[(size_t)n*K + k] : 0.f;
    __nv_bfloat16 h = __float2bfloat16(v);
    outh[i] = h;
    outl[i] = __float2bfloat16(v - __bfloat162float(h));
}

__global__ void k_rowsq_hl(const __nv_bfloat16* __restrict__ H, const __nv_bfloat16* __restrict__ Lo,
                           float* __restrict__ out, int rows, int Kp) {
    int w = (blockIdx.x * blockDim.x + threadIdx.x) >> 5;
    int lane = threadIdx.x & 31;
    if (w >= rows) return;
    const __nv_bfloat162* h2 = (const __nv_bfloat162*)(H  + (size_t)w * Kp);
    const __nv_bfloat162* l2 = (const __nv_bfloat162*)(Lo + (size_t)w * Kp);
    int K2 = Kp >> 1;
    float s = 0.f;
    for (int k = lane; k < K2; k += 32) {
        __nv_bfloat162 a = h2[k], b = l2[k];
        float v0 = __bfloat162float(a.x) + __bfloat162float(b.x);
        float v1 = __bfloat162float(a.y) + __bfloat162float(b.y);
        s += v0*v0 + v1*v1;
    }
    #pragma unroll
    for (int off = 16; off > 0; off >>= 1) s += __shfl_down_sync(0xFFFFFFFFu, s, off);
    if (lane == 0) out[w] = s;
}

// ---------------- HMMA bf16x3 GEMM with RBF epilogue + fused pass-1 histogram ----------------
#define A_TILE  32768
#define W_TILE  16384
#define BUF_BYTES2 98304

__device__ __forceinline__ void prefetch_rows(uint32_t sdst, const __nv_bfloat16* __restrict__ src,
                                              int row0, int Kpad, int k0, int tid, int nrows) {
    for (int i = tid; i < nrows*8; i += 256) {
        int row = i >> 3, c8 = i & 7;
        cp16(sdst + SWZ128(row*128 + c8*16),
             src + (size_t)(row0 + row) * Kpad + k0 + c8*8);
    }
}

template<int MODE>
__global__ void __launch_bounds__(256, 1)
k_gemm_mma(const __nv_bfloat16* __restrict__ Ah, const __nv_bfloat16* __restrict__ Al,
           const __nv_bfloat16* __restrict__ Wh, const __nv_bfloat16* __restrict__ Wl,
           const float* __restrict__ s2m, const float* __restrict__ s2n,
           float* __restrict__ out, int Kpad, int NC, int Mlim, int Nlim, int L, int NW,
           unsigned* __restrict__ h1)
{
    extern __shared__ char dsm[];
    const int tid  = threadIdx.x;
    const int wid  = tid >> 5;
    const int lane = tid & 31;
    const int m0 = blockIdx.y * 256;
    const int n0 = blockIdx.x * 128;
    const int m_w = (wid >> 1) * 64;
    const int n_w = (wid & 1) * 64;

    uint32_t sbase = smem_u32(dsm);

    float acc[4][8][4];
    #pragma unroll
    for (int a = 0; a < 4; a++)
        #pragma unroll
        for (int b = 0; b < 8; b++)
            #pragma unroll
            for (int c = 0; c < 4; c++) acc[a][b][c] = 0.f;

    const int g  = lane >> 3;
    const int rr = lane & 7;
    const int a_row  = m_w + (g & 1)*8 + rr;
    const int a_colg = (g >> 1) * 16;
    const int b_row  = n_w + (g >> 1)*8 + rr;
    const int b_colg = (g & 1) * 16;

    prefetch_rows(sbase,                    Ah, m0, Kpad, 0, tid, 256);
    prefetch_rows(sbase + A_TILE,           Al, m0, Kpad, 0, tid, 256);
    prefetch_rows(sbase + 2*A_TILE,         Wh, n0, Kpad, 0, tid, 128);
    prefetch_rows(sbase + 2*A_TILE+W_TILE,  Wl, n0, Kpad, 0, tid, 128);
    CP_COMMIT();

    for (int ch = 0; ch < NC; ch++) {
        if (ch + 1 < NC) {
            uint32_t nb = sbase + ((ch+1) & 1) * BUF_BYTES2;
            int k0 = (ch+1) * 64;
            prefetch_rows(nb,                   Ah, m0, Kpad, k0, tid, 256);
            prefetch_rows(nb + A_TILE,          Al, m0, Kpad, k0, tid, 256);
            prefetch_rows(nb + 2*A_TILE,        Wh, n0, Kpad, k0, tid, 128);
            prefetch_rows(nb + 2*A_TILE+W_TILE, Wl, n0, Kpad, k0, tid, 128);
            CP_COMMIT();
            CP_WAIT1();
        } else {
            CP_WAIT0();
        }
        __syncthreads();

        uint32_t buf = sbase + (ch & 1) * BUF_BYTES2;
        uint32_t tAh = buf, tAl = buf + A_TILE;
        uint32_t tWh = buf + 2*A_TILE, tWl = buf + 2*A_TILE + W_TILE;

        #pragma unroll
        for (int ks = 0; ks < 4; ks++) {
            int acol = ks*32 + a_colg;
            int bcol = ks*32 + b_colg;
            uint32_t ah[4][4], al[4][4];
            #pragma unroll
            for (int mf = 0; mf < 4; mf++) {
                uint32_t off = SWZ128((a_row + mf*16)*128 + acol);
                ldm_x4(ah[mf], tAh + off);
                ldm_x4(al[mf], tAl + off);
            }
            #pragma unroll
            for (int q = 0; q < 4; q++) {
                uint32_t off = SWZ128((b_row + q*16)*128 + bcol);
                uint32_t bh[4], bl[4];
                ldm_x4(bh, tWh + off);
                ldm_x4(bl, tWl + off);
                #pragma unroll
                for (int mf = 0; mf < 4; mf++)
                    #pragma unroll
                    for (int hlf = 0; hlf < 2; hlf++) {
                        int nf = q*2 + hlf;
                        mma_bf16(acc[mf][nf], ah[mf], &bh[hlf*2]);
                        mma_bf16(acc[mf][nf], ah[mf], &bl[hlf*2]);
                        mma_bf16(acc[mf][nf], al[mf], &bh[hlf*2]);
                    }
            }
        }
        __syncthreads();
    }

    unsigned* sh = (unsigned*)dsm;
    for (int i = tid; i < 4096; i += 256) sh[i] = 0u;
    __syncthreads();

    const int b_base = (MODE ? n0 : m0) / L;
    const int tg = lane >> 2, tk = lane & 3;
    #pragma unroll
    for (int mf = 0; mf < 4; mf++) {
        #pragma unroll
        for (int h = 0; h < 2; h++) {
            int m = m0 + m_w + mf*16 + tg + h*8;
            if (m >= Mlim) continue;
            float smv = s2m[m];
            if (MODE == 0) {
                int b = m / L;
                int l = m - b*L;
                float* ob = out + ((size_t)b*NW)*L + l;
                int slot = (b - b_base) << 11;
                #pragma unroll
                for (int nf = 0; nf < 8; nf++) {
                    #pragma unroll
                    for (int j = 0; j < 2; j++) {
                        int n = n0 + n_w + nf*8 + tk*2 + j;
                        if (n >= Nlim) continue;
                        float d2v = smv + s2n[n] - 2.0f * acc[mf][nf][h*2 + j];
                        float d = sqrtf(fmaxf(d2v, 0.0f));
                        ob[(size_t)n * L] = d;
                        hist_add(sh, (unsigned)(slot | (__float_as_uint(d) >> 21)));
                    }
                }
            } else {
                #pragma unroll
                for (int nf = 0; nf < 8; nf++) {
                    #pragma unroll
                    for (int j = 0; j < 2; j++) {
                        int n = n0 + n_w + nf*8 + tk*2 + j;
                        if (n >= Nlim) continue;
                        int b = n / L;
                        int l = n - b*L;
                        float d2v = smv + s2n[n] - 2.0f * acc[mf][nf][h*2 + j];
                        float d = sqrtf(fmaxf(d2v, 0.0f));
                        out[((size_t)b*NW + m)*L + l] = d;
                        hist_add(sh, (unsigned)(((b - b_base) << 11) | (__float_as_uint(d) >> 21)));
                    }
                }
            }
        }
    }
    __syncthreads();
    for (int i = tid; i < 4096; i += 256) {
        unsigned v = sh[i];
        int bb = b_base + (i >> 11);
        if (v && bb < BATCH) atomicAdd(&h1[bb*2048 + (i & 2047)], v);
    }
}

// ---------------- fused triangle + FC: chunked partials (deterministic) ----------------
__global__ void __launch_bounds__(256) k_fcpart(const float* __restrict__ fcw,
                                                const float* __restrict__ w3) {
    int chunk = blockIdx.x, b = blockIdx.y;
    int k0 = chunk * 9454;
    int k1 = k0 + 9454; if (k1 > 75625) k1 = 75625;
    float thr = g_thrA[b];
    float invw = 1.0f / w3[0];
    const float4* src = (const float4*)(g_d3 + (size_t)b * 302500);
    float acc[10];
    #pragma unroll
    for (int n = 0; n < 10; n++) acc[n] = 0.f;
    for (int k = k0 + threadIdx.x; k < k1; k += 256) {
        float4 v = src[k];
        float t0 = (v.x > thr ? 0.f : 1.f - v.x*invw);
        float t1 = (v.y > thr ? 0.f : 1.f - v.y*invw);
        float t2 = (v.z > thr ? 0.f : 1.f - v.z*invw);
        float t3 = (v.w > thr ? 0.f : 1.f - v.w*invw);
        #pragma unroll
        for (int n = 0; n < 10; n++) {
            float4 w = ((const float4*)(fcw + (size_t)n * 302500))[k];
            acc[n] += t0*w.x + t1*w.y + t2*w.z + t3*w.w;
        }
    }
    __shared__ float red[256];
    #pragma unroll
    for (int n = 0; n < 10; n++) {
        red[threadIdx.x] = acc[n];
        __syncthreads();
        for (int st = 128; st > 0; st >>= 1) {
            if (threadIdx.x < st) red[threadIdx.x] += red[threadIdx.x + st];
            __syncthreads();
        }
        if (threadIdx.x == 0) g_fcpart[((size_t)chunk*BATCH + b)*10 + n] = red[0];
        __syncthreads();
    }
}

__global__ void k_fcfin(const float* __restrict__ fcb, float* __restrict__ out) {
    int i = threadIdx.x;
    if (i >= BATCH*10) return;
    int n = i % 10;
    float s = fcb[n];
    for (int c = 0; c < FC_CHUNKS; c++) s += g_fcpart[(size_t)c*BATCH*10 + i];
    out[i] = s;
}

// ---------------- host side ----------------
static void run_select(unsigned* h1, const float* data, int Nper, int kk,
                       const float* wptr, float* thrOut) {
    k_scan1p<<<BATCH, 256>>>(h1, kk);
    k_hist<<<dim3(64, BATCH), 256>>>(data, Nper, 10, 2048, 21);
    k_scanp<<<BATCH, 256>>>(2048, 10, 0, nullptr, nullptr);
    k_hist<<<dim3(64, BATCH), 256>>>(data, Nper, 0, 1024, 10);
    k_scanp<<<BATCH, 256>>>(1024, 0, 1, wptr, thrOut);
}

extern "C" void kernel_launch(void* const* d_in, const int* in_sizes, int n_in,
                              void* d_out, int out_size) {
    const float* x       = (const float*)d_in[0];
    const float* rgb_w   = (const float*)d_in[1];
    const float* gray_w  = (const float*)d_in[2];
    const float* conv1_w = (const float*)d_in[3];
    const float* conv2_w = (const float*)d_in[4];
    const float* fc_w    = (const float*)d_in[5];
    const float* fc_b    = (const float*)d_in[6];
    const float* w1      = (const float*)d_in[7];
    const float* w2      = (const float*)d_in[8];
    const float* w3      = (const float*)d_in[9];
    float* out = (float*)d_out;

    void *pd1, *pd1g, *pact2, *pact3, *pd2, *pd3, *pthrA, *pthrB;
    void *pc1h, *pc1l, *pc2h, *pc2l, *pw1h, *pw1l, *pw2h, *pw2l;
    void *ps2a, *ps2b, *pwsq1, *pwsq2, *ph1a, *ph1b;
    cudaGetSymbolAddress(&pd1,   g_d1);
    cudaGetSymbolAddress(&pd1g,  g_d1g);
    cudaGetSymbolAddress(&pact2, g_act2);
    cudaGetSymbolAddress(&pact3, g_act3);
    cudaGetSymbolAddress(&pd2,   g_d2);
    cudaGetSymbolAddress(&pd3,   g_d3);
    cudaGetSymbolAddress(&pthrA, g_thrA);
    cudaGetSymbolAddress(&pthrB, g_thrB);
    cudaGetSymbolAddress(&pc1h,  g_col1h);
    cudaGetSymbolAddress(&pc1l,  g_col1l);
    cudaGetSymbolAddress(&pc2h,  g_col2h);
    cudaGetSymbolAddress(&pc2l,  g_col2l);
    cudaGetSymbolAddress(&pw1h,  g_w1h);
    cudaGetSymbolAddress(&pw1l,  g_w1l);
    cudaGetSymbolAddress(&pw2h,  g_w2h);
    cudaGetSymbolAddress(&pw2l,  g_w2l);
    cudaGetSymbolAddress(&ps2a,  g_s2a);
    cudaGetSymbolAddress(&ps2b,  g_s2b);
    cudaGetSymbolAddress(&pwsq1, g_wsq1);
    cudaGetSymbolAddress(&pwsq2, g_wsq2);
    cudaGetSymbolAddress(&ph1a,  g_h1a);
    cudaGetSymbolAddress(&ph1b,  g_h1b);

    cudaFuncSetAttribute(k_gemm_mma<0>, cudaFuncAttributeMaxDynamicSharedMemorySize, 196608);
    cudaFuncSetAttribute(k_gemm_mma<1>, cudaFuncAttributeMaxDynamicSharedMemorySize, 196608);
    cudaFuncSetAttribute(k_im2col_stage, cudaFuncAttributeMaxDynamicSharedMemorySize, 81008);

    // stage 1
    k_gray<<<(BATCH*10000 + 255)/256, 256>>>(x);
    k_rgbconv<<<1152, 256>>>(x, rgb_w);
    k_grayconv<<<1152, 256>>>(gray_w);
    // merged stage-1 selects (A: d1, B: d1g)
    k_scan1m<<<64, 256>>>(345600, 115200);
    k_histm<<<dim3(64, 64), 256>>>((const float*)pd1, (const float*)pd1g, 10, 2048, 21);
    k_scanm<<<64, 256>>>(2048, 10, 0, w1);
    k_histm<<<dim3(64, 64), 256>>>((const float*)pd1, (const float*)pd1g, 0, 1024, 10);
    k_scanm<<<64, 256>>>(1024, 0, 1, w1);
    k_sfm1<<<(BATCH*230400 + 255)/256, 256>>>(w1);

    // conv1 (RBF, k=3, pad=1): (B,100,48,48) -> (B,225,48,48)
    k_im2col_stage<<<1536, 256, 63600>>>((const float*)pact2,
        (__nv_bfloat16*)pc1h, (__nv_bfloat16*)pc1l, (float*)ps2a,
        100, 48, 48, 48, 48, 1, 900, 960);
    k_wprep<<<(256*960 + 255)/256, 256>>>(conv1_w, (__nv_bfloat16*)pw1h, (__nv_bfloat16*)pw1l,
                                          225, 900, 256, 960);
    k_rowsq_hl<<<(256*32 + 255)/256, 256>>>((const __nv_bfloat16*)pw1h, (const __nv_bfloat16*)pw1l,
                                            (float*)pwsq1, 256, 960);
    k_gemm_mma<1><<<dim3(576, 1), 256, 196608>>>(
        (const __nv_bfloat16*)pw1h, (const __nv_bfloat16*)pw1l,
        (const __nv_bfloat16*)pc1h, (const __nv_bfloat16*)pc1l,
        (const float*)pwsq1, (const float*)ps2a, (float*)pd2,
        960, 15, 225, 73728, 2304, 225, (unsigned*)ph1a);
    run_select((unsigned*)ph1a, (const float*)pd2, 518400, 207360, w2, (float*)pthrA);
    k_sfm2<<<(BATCH*129600 + 255)/256, 256>>>(w2);

    // conv2 (RBF, k=3, pad=0): (B,225,24,24) -> (B,625,22,22)
    k_im2col_stage<<<704, 256, 81008>>>((const float*)pact3,
        (__nv_bfloat16*)pc2h, (__nv_bfloat16*)pc2l, (float*)ps2b,
        225, 24, 24, 22, 22, 0, 2025, 2048);
    k_wprep<<<(640*2048 + 255)/256, 256>>>(conv2_w, (__nv_bfloat16*)pw2h, (__nv_bfloat16*)pw2l,
                                           625, 2025, 640, 2048);
    k_rowsq_hl<<<(640*32 + 255)/256, 256>>>((const __nv_bfloat16*)pw2h, (const __nv_bfloat16*)pw2l,
                                            (float*)pwsq2, 640, 2048);
    k_gemm_mma<0><<<dim3(5, 61), 256, 196608>>>(
        (const __nv_bfloat16*)pc2h, (const __nv_bfloat16*)pc2l,
        (const __nv_bfloat16*)pw2h, (const __nv_bfloat16*)pw2l,
        (const float*)ps2b, (const float*)pwsq2, (float*)pd3,
        2048, 32, 15488, 625, 484, 625, (unsigned*)ph1a);
    run_select((unsigned*)ph1a, (const float*)pd3, 302500, 121000, w3, (float*)pthrA);

    // fused triangle + FC (chunked partials + deterministic finisher)
    k_fcpart<<<dim3(FC_CHUNKS, BATCH), 256>>>(fc_w, w3);
    k_fcfin<<<1, 320>>>(fc_b, out);
}

// round 11
// speedup vs baseline: 1.0599x; 1.0599x over previous
#include <cuda_runtime.h>
#include <cuda_bf16.h>
#include <math.h>
#include <stdint.h>

#define BATCH 32

// ---------------- persistent scratch (device globals; no allocation) ----------------
__device__ float g_gray[BATCH*10000];
__device__ float g_d1 [BATCH*691200];          // rgb distances  (B,75,96,96)
__device__ float g_d1g[BATCH*230400];          // gray distances (B,25,96,96)
__device__ float g_act2[BATCH*230400];         // after triangle+sfm (B,100,48,48)
__device__ float g_act3[BATCH*129600];         // after triangle+sfm (B,225,24,24)
__device__ float g_d2 [BATCH*518400];          // conv1 distances (B,225,48,48)
__device__ float g_d3 [BATCH*302500];          // conv2 distances (B,625,22,22)

// bf16 hi/lo split operands (padded; conv2 M padded 15488->15616 for 256-row tiles)
__device__ __align__(16) __nv_bfloat16 g_col1h[73728*960];
__device__ __align__(16) __nv_bfloat16 g_col1l[73728*960];
__device__ __align__(16) __nv_bfloat16 g_col2h[15616*2048];
__device__ __align__(16) __nv_bfloat16 g_col2l[15616*2048];
__device__ __align__(16) __nv_bfloat16 g_w1h[256*960];
__device__ __align__(16) __nv_bfloat16 g_w1l[256*960];
__device__ __align__(16) __nv_bfloat16 g_w2h[640*2048];
__device__ __align__(16) __nv_bfloat16 g_w2l[640*2048];
__device__ float g_s2a [73728];
__device__ float g_s2b [15616];
__device__ float g_wsq1[256];
__device__ float g_wsq2[640];

__device__ unsigned g_histo[BATCH*2048];   // passes 2/3 (zero-invariant)
__device__ unsigned g_h1a[BATCH*2048];     // pass-1 histo (producer-filled) A
__device__ unsigned g_h1b[BATCH*2048];     // pass-1 histo (producer-filled) B
__device__ unsigned g_prefix[BATCH];
__device__ int      g_krem[BATCH];
__device__ float    g_thrA[BATCH];
__device__ float    g_thrB[BATCH];

#define FC_CHUNKS 16
__device__ float g_fcpart[FC_CHUNKS*BATCH*10];

// ---------------- ptx helpers (plain sm_103-safe: no tcgen05) ----------------
__device__ __forceinline__ uint32_t smem_u32(const void* p) {
    uint32_t a;
    asm("{ .reg .u64 t; cvta.to.shared.u64 t, %1; cvt.u32.u64 %0, t; }" : "=r"(a) : "l"(p));
    return a;
}
__device__ __forceinline__ void cp16(uint32_t dst, const void* src) {
    asm volatile("cp.async.cg.shared.global [%0], [%1], 16;" :: "r"(dst), "l"(src));
}
#define CP_COMMIT() asm volatile("cp.async.commit_group;" ::: "memory")
#define CP_WAIT1()  asm volatile("cp.async.wait_group 1;" ::: "memory")
#define CP_WAIT0()  asm volatile("cp.async.wait_group 0;" ::: "memory")

__device__ __forceinline__ void ldm_x4(uint32_t* r, uint32_t addr) {
    asm volatile("ldmatrix.sync.aligned.m8n8.x4.shared.b16 {%0,%1,%2,%3}, [%4];"
                 : "=r"(r[0]), "=r"(r[1]), "=r"(r[2]), "=r"(r[3]) : "r"(addr));
}
__device__ __forceinline__ void mma_bf16(float* d, const uint32_t* a, const uint32_t* b) {
    asm volatile("mma.sync.aligned.m16n8k16.row.col.f32.bf16.bf16.f32 "
                 "{%0,%1,%2,%3}, {%4,%5,%6,%7}, {%8,%9}, {%0,%1,%2,%3};"
                 : "+f"(d[0]), "+f"(d[1]), "+f"(d[2]), "+f"(d[3])
                 : "r"(a[0]), "r"(a[1]), "r"(a[2]), "r"(a[3]), "r"(b[0]), "r"(b[1]));
}
#define SWZ128(x) ((x) ^ (((x) >> 3) & 0x70))

__device__ __forceinline__ float tri_val(float v, float thr, float invw) {
    return (v > thr) ? 0.0f : 1.0f - v * invw;
}

// ---------------- parallel k-th-bin search (256-thread block) ----------------
__device__ __forceinline__ unsigned block_kth(const unsigned* hist, int nbins, unsigned k,
                                              unsigned* scanbuf, int* sel_sm, unsigned* krem_sm,
                                              int tid) {
    int per = nbins >> 8;
    int base = tid * per;
    unsigned own = 0;
    for (int j = 0; j < per; j++) own += hist[base + j];
    scanbuf[tid] = own;
    __syncthreads();
    for (int off = 1; off < 256; off <<= 1) {
        unsigned v = (tid >= off) ? scanbuf[tid - off] : 0u;
        __syncthreads();
        scanbuf[tid] += v;
        __syncthreads();
    }
    unsigned incl = scanbuf[tid];
    unsigned excl = incl - own;
    if (excl < k && incl >= k) {
        unsigned c = excl;
        for (int j = 0; j < per; j++) {
            unsigned v = hist[base + j];
            if (c + v >= k) { *sel_sm = base + j; *krem_sm = k - c; break; }
            c += v;
        }
    }
    __syncthreads();
    return (unsigned)*sel_sm;
}

// ---------------- grayscale ----------------
__global__ void k_gray(const float* __restrict__ x) {
    int i = blockIdx.x * blockDim.x + threadIdx.x;
    if (i >= BATCH*10000) return;
    int b = i / 10000, p = i - b*10000;
    const float* xb = x + (size_t)b * 30000;
    g_gray[i] = 0.2989f*xb[p] + 0.587f*xb[10000+p] + 0.114f*xb[20000+p];
}

// ---------------- rgb conv (5x5) -> d1, with fused pass-1 histogram ----------------
__global__ void k_rgbconv(const float* __restrict__ x, const float* __restrict__ rgb_w) {
    __shared__ float sw[225];
    __shared__ float swsq[75];
    __shared__ unsigned hist[2048];
    int t = threadIdx.x;
    if (t < 225) sw[t] = rgb_w[t];
    for (int j = t; j < 2048; j += 256) hist[j] = 0u;
    __syncthreads();
    if (t < 75) {
        float a = sw[t*3], b2 = sw[t*3+1], c = sw[t*3+2];
        swsq[t] = a*a + b2*b2 + c*c;
    }
    __syncthreads();
    int i = blockIdx.x * 256 + t;
    int b = i / 9216, l = i - b*9216;
    int oy = l / 96, ox = l - oy*96;
    const float* xb = x + (size_t)b * 30000;
    float s1[3];
    float s2 = 0.f;
    #pragma unroll
    for (int c = 0; c < 3; c++) {
        float sc = 0.f;
        const float* xc = xb + c*10000;
        #pragma unroll
        for (int dy = 0; dy < 5; dy++) {
            const float* row = xc + (oy+dy)*100 + ox;
            #pragma unroll
            for (int dx = 0; dx < 5; dx++) { float v = row[dx]; sc += v; s2 += v*v; }
        }
        s1[c] = sc;
    }
    float* o = g_d1 + (size_t)b * 691200 + l;
    #pragma unroll 5
    for (int f = 0; f < 75; f++) {
        float d2 = s2 + 25.0f*swsq[f]
                 - 2.0f*(sw[f*3]*s1[0] + sw[f*3+1]*s1[1] + sw[f*3+2]*s1[2]);
        float d = sqrtf(fmaxf(d2, 0.0f));
        o[(size_t)f*9216] = d;
        atomicAdd(&hist[__float_as_uint(d) >> 21], 1u);
    }
    __syncthreads();
    int bb = blockIdx.x / 36;
    for (int j = t; j < 2048; j += 256)
        if (hist[j]) atomicAdd(&g_h1a[bb*2048 + j], hist[j]);
}

// ---------------- gray RBF conv (5x5) -> d1g, with fused pass-1 histogram ----------------
__global__ void k_grayconv(const float* __restrict__ gray_w) {
    __shared__ float sw[625];
    __shared__ float swsq[25];
    __shared__ unsigned hist[2048];
    int t = threadIdx.x;
    for (int j = t; j < 625; j += 256) sw[j] = gray_w[j];
    for (int j = t; j < 2048; j += 256) hist[j] = 0u;
    __syncthreads();
    if (t < 25) {
        float s = 0.f;
        for (int k = 0; k < 25; k++) { float v = sw[t*25+k]; s += v*v; }
        swsq[t] = s;
    }
    __syncthreads();
    int i = blockIdx.x * 256 + t;
    int b = i / 9216, l = i - b*9216;
    int oy = l / 96, ox = l - oy*96;
    const float* gb = g_gray + (size_t)b * 10000;
    float p[25];
    float pn = 0.f;
    #pragma unroll
    for (int dy = 0; dy < 5; dy++) {
        const float* row = gb + (oy+dy)*100 + ox;
        #pragma unroll
        for (int dx = 0; dx < 5; dx++) { float v = row[dx]; p[dy*5+dx] = v; pn += v*v; }
    }
    float* o = g_d1g + (size_t)b * 230400 + l;
    #pragma unroll 5
    for (int f = 0; f < 25; f++) {
        float dot = 0.f;
        #pragma unroll
        for (int k = 0; k < 25; k++) dot += sw[f*25+k] * p[k];
        float d = sqrtf(fmaxf(pn + swsq[f] - 2.0f*dot, 0.0f));
        o[(size_t)f*9216] = d;
        atomicAdd(&hist[__float_as_uint(d) >> 21], 1u);
    }
    __syncthreads();
    int bb = blockIdx.x / 36;
    for (int j = t; j < 2048; j += 256)
        if (hist[j]) atomicAdd(&g_h1b[bb*2048 + j], hist[j]);
}

// ---------------- select: parallel scan of pass-1 histo (producer-filled), init state ----------------
__global__ void k_scan1p(unsigned* __restrict__ h1, int kk) {
    __shared__ unsigned scanbuf[256];
    __shared__ int ssel;
    __shared__ unsigned skrem;
    int b = blockIdx.x, tid = threadIdx.x;
    unsigned* h = h1 + b*2048;
    unsigned sel = block_kth(h, 2048, (unsigned)kk, scanbuf, &ssel, &skrem, tid);
    if (tid == 0) { g_prefix[b] = sel << 21; g_krem[b] = (int)skrem; }
    __syncthreads();
    for (int j = tid; j < 2048; j += 256) h[j] = 0u;
}

// ---------------- select: filtered histogram (passes 2/3), uint4 loads ----------------
__global__ void k_hist(const float* __restrict__ data, int Nper, int shift, int nbins, int hichk) {
    __shared__ unsigned sh[2048];
    int t = threadIdx.x;
    for (int j = t; j < nbins; j += blockDim.x) sh[j] = 0u;
    __syncthreads();
    int b = blockIdx.y;
    unsigned want = g_prefix[b] >> hichk;
    const uint4* p = (const uint4*)(data + (size_t)b * Nper);
    unsigned mask = (unsigned)nbins - 1u;
    int n4 = Nper >> 2;
    for (int i = blockIdx.x * blockDim.x + t; i < n4; i += gridDim.x * blockDim.x) {
        uint4 u = p[i];
        if ((u.x >> hichk) == want) atomicAdd(&sh[(u.x >> shift) & mask], 1u);
        if ((u.y >> hichk) == want) atomicAdd(&sh[(u.y >> shift) & mask], 1u);
        if ((u.z >> hichk) == want) atomicAdd(&sh[(u.z >> shift) & mask], 1u);
        if ((u.w >> hichk) == want) atomicAdd(&sh[(u.w >> shift) & mask], 1u);
    }
    __syncthreads();
    for (int j = t; j < nbins; j += blockDim.x)
        if (sh[j]) atomicAdd(&g_histo[b*2048+j], sh[j]);
}

// ---------------- select: parallel scan of filtered histo ----------------
__global__ void k_scanp(int nbins, int shift, int finalize, const float* wptr, float* thrOut) {
    __shared__ unsigned scanbuf[256];
    __shared__ int ssel;
    __shared__ unsigned skrem;
    int b = blockIdx.x, tid = threadIdx.x;
    unsigned* h = &g_histo[b*2048];
    unsigned sel = block_kth(h, nbins, (unsigned)g_krem[b], scanbuf, &ssel, &skrem, tid);
    if (tid == 0) {
        g_prefix[b] |= sel << shift;
        g_krem[b] = (int)skrem;
        if (finalize) thrOut[b] = fminf(__uint_as_float(g_prefix[b]), wptr[0]);
    }
    __syncthreads();
    for (int j = tid; j < 2048; j += 256) h[j] = 0u;
}

// ---------------- fused triangle + sfm (stage 1) ----------------
__global__ void k_sfm1(const float* __restrict__ w1) {
    int i = blockIdx.x * blockDim.x + threadIdx.x;
    if (i >= BATCH*230400) return;
    int b = i / 230400;
    int r = i - b*230400;
    int c = r / 2304;
    int l = r - c*2304;
    int oy = l / 48, ox = l - oy*48;
    float thr;
    const float* src;
    if (c < 75) { thr = g_thrA[b]; src = g_d1  + (size_t)b*691200 + (size_t)c*9216; }
    else        { thr = g_thrB[b]; src = g_d1g + (size_t)b*230400 + (size_t)(c-75)*9216; }
    float invw = 1.0f / w1[0];
    int y = 2*oy, x2 = 2*ox;
    float v00 = tri_val(src[y*96 + x2],       thr, invw);
    float v01 = tri_val(src[y*96 + x2 + 1],   thr, invw);
    float v10 = tri_val(src[(y+1)*96 + x2],   thr, invw);
    float v11 = tri_val(src[(y+1)*96 + x2+1], thr, invw);
    g_act2[i] = 0.25f * (0.90f*v00 + 0.93f*v01 + 0.96f*v10 + 0.99f*v11);
}

// ---------------- fused triangle + sfm (stage 2) ----------------
__global__ void k_sfm2(const float* __restrict__ w2) {
    int i = blockIdx.x * blockDim.x + threadIdx.x;
    if (i >= BATCH*129600) return;
    int b = i / 129600;
    int r = i - b*129600;
    int c = r / 576;
    int l = r - c*576;
    int oy = l / 24, ox = l - oy*24;
    float thr = g_thrA[b];
    float invw = 1.0f / w2[0];
    const float* src = g_d2 + ((size_t)b*225 + c) * 2304;
    int y = 2*oy, x2 = 2*ox;
    float v00 = tri_val(src[y*48 + x2],       thr, invw);
    float v01 = tri_val(src[y*48 + x2 + 1],   thr, invw);
    float v10 = tri_val(src[(y+1)*48 + x2],   thr, invw);
    float v11 = tri_val(src[(y+1)*48 + x2+1], thr, invw);
    g_act3[i] = 0.25f * (0.90f*v00 + 0.93f*v01 + 0.96f*v10 + 0.99f*v11);
}

// ---------------- staged-smem im2col -> bf16 hi/lo + row s2 ----------------
__global__ void __launch_bounds__(256) k_im2col_stage(
    const float* __restrict__ in,
    __nv_bfloat16* __restrict__ outh, __nv_bfloat16* __restrict__ outl,
    float* __restrict__ s2out,
    int C, int Hin, int Win, int oh, int ow, int pad, int Ktrue, int Kpad)
{
    extern __shared__ char smraw[];
    float* sm = (float*)smraw;
    int W2 = Win + 2*pad;
    int stageN = C * 3 * W2;
    int* kcol = (int*)(smraw + (size_t)stageN * 4);

    int bid = blockIdx.x;
    int b = bid / oh, oy = bid - b*oh;
    int tid = threadIdx.x;

    for (int k = tid; k < Ktrue; k += 256) {
        int c = k / 9; int r = k - c*9; int di = r / 3; int dj = r - di*3;
        kcol[k] = (c*3 + di)*W2 + dj;
    }
    const float* inb = in + (size_t)b * C * Hin * Win;
    for (int idx = tid; idx < stageN; idx += 256) {
        int c = idx / (3*W2); int rem = idx - c*3*W2;
        int dy = rem / W2; int xx = rem - dy*W2;
        int iy = oy + dy - pad; int ix = xx - pad;
        float v = 0.f;
        if (iy >= 0 && iy < Hin && ix >= 0 && ix < Win)
            v = inb[((size_t)c*Hin + iy)*Win + ix];
        sm[idx] = v;
    }
    __syncthreads();

    int L = oh * ow;
    int mbase = b*L + oy*ow;
    int KH = Kpad >> 1;
    int total = ow * KH;
    int ox = tid / KH, p = tid - ox*KH;
    for (int j = tid; j < total; j += 256) {
        int k0 = p*2, k1 = k0 + 1;
        float v0 = (k0 < Ktrue) ? sm[kcol[k0] + ox] : 0.f;
        float v1 = (k1 < Ktrue) ? sm[kcol[k1] + ox] : 0.f;
        __nv_bfloat16 h0 = __float2bfloat16(v0);
        __nv_bfloat16 h1 = __float2bfloat16(v1);
        __nv_bfloat16 l0 = __float2bfloat16(v0 - __bfloat162float(h0));
        __nv_bfloat16 l1 = __float2bfloat16(v1 - __bfloat162float(h1));
        size_t off = (size_t)(mbase + ox) * Kpad + k0;
        *(__nv_bfloat162*)(outh + off) = __nv_bfloat162(h0, h1);
        *(__nv_bfloat162*)(outl + off) = __nv_bfloat162(l0, l1);
        p += 256;
        if (p >= KH) { p -= KH; ox++; }
    }

    int wid = tid >> 5, lane = tid & 31;
    for (int oxx = wid; oxx < ow; oxx += 8) {
        float s = 0.f;
        for (int k = lane; k < Ktrue; k += 32) {
            float v = sm[kcol[k] + oxx];
            __nv_bfloat16 h = __float2bfloat16(v);
            float fh = __bfloat162float(h);
            __nv_bfloat16 lo = __float2bfloat16(v - fh);
            float rec = fh + __bfloat162float(lo);
            s += rec*rec;
        }
        #pragma unroll
        for (int o2 = 16; o2 > 0; o2 >>= 1) s += __shfl_down_sync(0xFFFFFFFFu, s, o2);
        if (lane == 0) s2out[mbase + oxx] = s;
    }
}

// ---------------- weight prep: pad + bf16 split ----------------
__global__ void k_wprep(const float* __restrict__ w,
                        __nv_bfloat16* __restrict__ outh, __nv_bfloat16* __restrict__ outl,
                        int N, int K, int Npad, int Kpad) {
    int i = blockIdx.x * blockDim.x + threadIdx.x;
    if (i >= Npad*Kpad) return;
    int n = i / Kpad, k = i - n*Kpad;
    float v = (n < N && k < K) ? w[(size_t)n*K + k] : 0.f;
    __nv_bfloat16 h = __float2bfloat16(v);
    outh[i] = h;
    outl[i] = __float2bfloat16(v - __bfloat162float(h));
}

__global__ void k_rowsq_hl(const __nv_bfloat16* __restrict__ H, const __nv_bfloat16* __restrict__ Lo,
                           float* __restrict__ out, int rows, int Kp) {
    int w = (blockIdx.x * blockDim.x + threadIdx.x) >> 5;
    int lane = threadIdx.x & 31;
    if (w >= rows) return;
    const __nv_bfloat162* h2 = (const __nv_bfloat162*)(H  + (size_t)w * Kp);
    const __nv_bfloat162* l2 = (const __nv_bfloat162*)(Lo + (size_t)w * Kp);
    int K2 = Kp >> 1;
    float s = 0.f;
    for (int k = lane; k < K2; k += 32) {
        __nv_bfloat162 a = h2[k], b = l2[k];
        float v0 = __bfloat162float(a.x) + __bfloat162float(b.x);
        float v1 = __bfloat162float(a.y) + __bfloat162float(b.y);
        s += v0*v0 + v1*v1;
    }
    #pragma unroll
    for (int off = 16; off > 0; off >>= 1) s += __shfl_down_sync(0xFFFFFFFFu, s, off);
    if (lane == 0) out[w] = s;
}

// ---------------- HMMA bf16x3 GEMM with RBF epilogue + fused pass-1 histogram ----------------
#define A_TILE  32768
#define W_TILE  16384
#define BUF_BYTES2 98304

__device__ __forceinline__ void prefetch_rows(uint32_t sdst, const __nv_bfloat16* __restrict__ src,
                                              int row0, int Kpad, int k0, int tid, int nrows) {
    for (int i = tid; i < nrows*8; i += 256) {
        int row = i >> 3, c8 = i & 7;
        cp16(sdst + SWZ128(row*128 + c8*16),
             src + (size_t)(row0 + row) * Kpad + k0 + c8*8);
    }
}

template<int MODE>
__global__ void __launch_bounds__(256, 1)
k_gemm_mma(const __nv_bfloat16* __restrict__ Ah, const __nv_bfloat16* __restrict__ Al,
           const __nv_bfloat16* __restrict__ Wh, const __nv_bfloat16* __restrict__ Wl,
           const float* __restrict__ s2m, const float* __restrict__ s2n,
           float* __restrict__ out, int Kpad, int NC, int Mlim, int Nlim, int L, int NW,
           unsigned* __restrict__ h1)
{
    extern __shared__ char dsm[];
    const int tid  = threadIdx.x;
    const int wid  = tid >> 5;
    const int lane = tid & 31;
    const int m0 = blockIdx.y * 256;
    const int n0 = blockIdx.x * 128;
    const int m_w = (wid >> 1) * 64;
    const int n_w = (wid & 1) * 64;

    uint32_t sbase = smem_u32(dsm);

    float acc[4][8][4];
    #pragma unroll
    for (int a = 0; a < 4; a++)
        #pragma unroll
        for (int b = 0; b < 8; b++)
            #pragma unroll
            for (int c = 0; c < 4; c++) acc[a][b][c] = 0.f;

    const int g  = lane >> 3;
    const int rr = lane & 7;
    const int a_row  = m_w + (g & 1)*8 + rr;
    const int a_colg = (g >> 1) * 16;
    const int b_row  = n_w + (g >> 1)*8 + rr;
    const int b_colg = (g & 1) * 16;

    prefetch_rows(sbase,                    Ah, m0, Kpad, 0, tid, 256);
    prefetch_rows(sbase + A_TILE,           Al, m0, Kpad, 0, tid, 256);
    prefetch_rows(sbase + 2*A_TILE,         Wh, n0, Kpad, 0, tid, 128);
    prefetch_rows(sbase + 2*A_TILE+W_TILE,  Wl, n0, Kpad, 0, tid, 128);
    CP_COMMIT();

    for (int ch = 0; ch < NC; ch++) {
        if (ch + 1 < NC) {
            uint32_t nb = sbase + ((ch+1) & 1) * BUF_BYTES2;
            int k0 = (ch+1) * 64;
            prefetch_rows(nb,                   Ah, m0, Kpad, k0, tid, 256);
            prefetch_rows(nb + A_TILE,          Al, m0, Kpad, k0, tid, 256);
            prefetch_rows(nb + 2*A_TILE,        Wh, n0, Kpad, k0, tid, 128);
            prefetch_rows(nb + 2*A_TILE+W_TILE, Wl, n0, Kpad, k0, tid, 128);
            CP_COMMIT();
            CP_WAIT1();
        } else {
            CP_WAIT0();
        }
        __syncthreads();

        uint32_t buf = sbase + (ch & 1) * BUF_BYTES2;
        uint32_t tAh = buf, tAl = buf + A_TILE;
        uint32_t tWh = buf + 2*A_TILE, tWl = buf + 2*A_TILE + W_TILE;

        #pragma unroll
        for (int ks = 0; ks < 4; ks++) {
            int acol = ks*32 + a_colg;
            int bcol = ks*32 + b_colg;
            uint32_t ah[4][4], al[4][4];
            #pragma unroll
            for (int mf = 0; mf < 4; mf++) {
                uint32_t off = SWZ128((a_row + mf*16)*128 + acol);
                ldm_x4(ah[mf], tAh + off);
                ldm_x4(al[mf], tAl + off);
            }
            #pragma unroll
            for (int q = 0; q < 4; q++) {
                uint32_t off = SWZ128((b_row + q*16)*128 + bcol);
                uint32_t bh[4], bl[4];
                ldm_x4(bh, tWh + off);
                ldm_x4(bl, tWl + off);
                #pragma unroll
                for (int mf = 0; mf < 4; mf++)
                    #pragma unroll
                    for (int hlf = 0; hlf < 2; hlf++) {
                        int nf = q*2 + hlf;
                        mma_bf16(acc[mf][nf], ah[mf], &bh[hlf*2]);
                        mma_bf16(acc[mf][nf], ah[mf], &bl[hlf*2]);
                        mma_bf16(acc[mf][nf], al[mf], &bh[hlf*2]);
                    }
            }
        }
        __syncthreads();
    }

    unsigned* sh = (unsigned*)dsm;
    for (int i = tid; i < 4096; i += 256) sh[i] = 0u;
    __syncthreads();

    const int b_base = (MODE ? n0 : m0) / L;
    const int tg = lane >> 2, tk = lane & 3;
    #pragma unroll
    for (int mf = 0; mf < 4; mf++) {
        #pragma unroll
        for (int h = 0; h < 2; h++) {
            int m = m0 + m_w + mf*16 + tg + h*8;
            if (m >= Mlim) continue;
            float smv = s2m[m];
            if (MODE == 0) {
                int b = m / L;
                int l = m - b*L;
                float* ob = out + ((size_t)b*NW)*L + l;
                int slot = (b - b_base) << 11;
                #pragma unroll
                for (int nf = 0; nf < 8; nf++) {
                    #pragma unroll
                    for (int j = 0; j < 2; j++) {
                        int n = n0 + n_w + nf*8 + tk*2 + j;
                        if (n >= Nlim) continue;
                        float d2v = smv + s2n[n] - 2.0f * acc[mf][nf][h*2 + j];
                        float d = sqrtf(fmaxf(d2v, 0.0f));
                        ob[(size_t)n * L] = d;
                        atomicAdd(&sh[slot | (__float_as_uint(d) >> 21)], 1u);
                    }
                }
            } else {
                #pragma unroll
                for (int nf = 0; nf < 8; nf++) {
                    #pragma unroll
                    for (int j = 0; j < 2; j++) {
                        int n = n0 + n_w + nf*8 + tk*2 + j;
                        if (n >= Nlim) continue;
                        int b = n / L;
                        int l = n - b*L;
                        float d2v = smv + s2n[n] - 2.0f * acc[mf][nf][h*2 + j];
                        float d = sqrtf(fmaxf(d2v, 0.0f));
                        out[((size_t)b*NW + m)*L + l] = d;
                        atomicAdd(&sh[((b - b_base) << 11) | (__float_as_uint(d) >> 21)], 1u);
                    }
                }
            }
        }
    }
    __syncthreads();
    for (int i = tid; i < 4096; i += 256) {
        unsigned v = sh[i];
        int bb = b_base + (i >> 11);
        if (v && bb < BATCH) atomicAdd(&h1[bb*2048 + (i & 2047)], v);
    }
}

// ---------------- fused triangle + FC: chunked partials (deterministic) ----------------
#define FC_CHUNK_LEN 4727   // ceil(75625/16); 16*4727 = 75632 >= 75625
__global__ void __launch_bounds__(256) k_fcpart(const float* __restrict__ fcw,
                                                const float* __restrict__ w3) {
    int chunk = blockIdx.x, b = blockIdx.y;
    int k0 = chunk * FC_CHUNK_LEN;
    int k1 = k0 + FC_CHUNK_LEN; if (k1 > 75625) k1 = 75625;
    float thr = g_thrA[b];
    float invw = 1.0f / w3[0];
    const float4* src = (const float4*)(g_d3 + (size_t)b * 302500);
    float acc[10];
    #pragma unroll
    for (int n = 0; n < 10; n++) acc[n] = 0.f;
    for (int k = k0 + threadIdx.x; k < k1; k += 256) {
        float4 v = src[k];
        float t0 = (v.x > thr ? 0.f : 1.f - v.x*invw);
        float t1 = (v.y > thr ? 0.f : 1.f - v.y*invw);
        float t2 = (v.z > thr ? 0.f : 1.f - v.z*invw);
        float t3 = (v.w > thr ? 0.f : 1.f - v.w*invw);
        #pragma unroll
        for (int n = 0; n < 10; n++) {
            float4 w = ((const float4*)(fcw + (size_t)n * 302500))[k];
            acc[n] += t0*w.x + t1*w.y + t2*w.z + t3*w.w;
        }
    }
    __shared__ float red[256];
    #pragma unroll
    for (int n = 0; n < 10; n++) {
        red[threadIdx.x] = acc[n];
        __syncthreads();
        for (int st = 128; st > 0; st >>= 1) {
            if (threadIdx.x < st) red[threadIdx.x] += red[threadIdx.x + st];
            __syncthreads();
        }
        if (threadIdx.x == 0) g_fcpart[((size_t)chunk*BATCH + b)*10 + n] = red[0];
        __syncthreads();
    }
}

__global__ void k_fcfin(const float* __restrict__ fcb, float* __restrict__ out) {
    int i = threadIdx.x;
    if (i >= BATCH*10) return;
    int n = i % 10;
    float s = fcb[n];
    for (int c = 0; c < FC_CHUNKS; c++) s += g_fcpart[(size_t)c*BATCH*10 + i];
    out[i] = s;
}

// ---------------- host side ----------------
static void run_select(unsigned* h1, const float* data, int Nper, int kk,
                       const float* wptr, float* thrOut) {
    k_scan1p<<<BATCH, 256>>>(h1, kk);
    k_hist<<<dim3(64, BATCH), 256>>>(data, Nper, 10, 2048, 21);
    k_scanp<<<BATCH, 256>>>(2048, 10, 0, nullptr, nullptr);
    k_hist<<<dim3(64, BATCH), 256>>>(data, Nper, 0, 1024, 10);
    k_scanp<<<BATCH, 256>>>(1024, 0, 1, wptr, thrOut);
}

extern "C" void kernel_launch(void* const* d_in, const int* in_sizes, int n_in,
                              void* d_out, int out_size) {
    const float* x       = (const float*)d_in[0];
    const float* rgb_w   = (const float*)d_in[1];
    const float* gray_w  = (const float*)d_in[2];
    const float* conv1_w = (const float*)d_in[3];
    const float* conv2_w = (const float*)d_in[4];
    const float* fc_w    = (const float*)d_in[5];
    const float* fc_b    = (const float*)d_in[6];
    const float* w1      = (const float*)d_in[7];
    const float* w2      = (const float*)d_in[8];
    const float* w3      = (const float*)d_in[9];
    float* out = (float*)d_out;

    void *pd1, *pd1g, *pact2, *pact3, *pd2, *pd3, *pthrA, *pthrB;
    void *pc1h, *pc1l, *pc2h, *pc2l, *pw1h, *pw1l, *pw2h, *pw2l;
    void *ps2a, *ps2b, *pwsq1, *pwsq2, *ph1a, *ph1b;
    cudaGetSymbolAddress(&pd1,   g_d1);
    cudaGetSymbolAddress(&pd1g,  g_d1g);
    cudaGetSymbolAddress(&pact2, g_act2);
    cudaGetSymbolAddress(&pact3, g_act3);
    cudaGetSymbolAddress(&pd2,   g_d2);
    cudaGetSymbolAddress(&pd3,   g_d3);
    cudaGetSymbolAddress(&pthrA, g_thrA);
    cudaGetSymbolAddress(&pthrB, g_thrB);
    cudaGetSymbolAddress(&pc1h,  g_col1h);
    cudaGetSymbolAddress(&pc1l,  g_col1l);
    cudaGetSymbolAddress(&pc2h,  g_col2h);
    cudaGetSymbolAddress(&pc2l,  g_col2l);
    cudaGetSymbolAddress(&pw1h,  g_w1h);
    cudaGetSymbolAddress(&pw1l,  g_w1l);
    cudaGetSymbolAddress(&pw2h,  g_w2h);
    cudaGetSymbolAddress(&pw2l,  g_w2l);
    cudaGetSymbolAddress(&ps2a,  g_s2a);
    cudaGetSymbolAddress(&ps2b,  g_s2b);
    cudaGetSymbolAddress(&pwsq1, g_wsq1);
    cudaGetSymbolAddress(&pwsq2, g_wsq2);
    cudaGetSymbolAddress(&ph1a,  g_h1a);
    cudaGetSymbolAddress(&ph1b,  g_h1b);

    cudaFuncSetAttribute(k_gemm_mma<0>, cudaFuncAttributeMaxDynamicSharedMemorySize, 196608);
    cudaFuncSetAttribute(k_gemm_mma<1>, cudaFuncAttributeMaxDynamicSharedMemorySize, 196608);
    cudaFuncSetAttribute(k_im2col_stage, cudaFuncAttributeMaxDynamicSharedMemorySize, 81008);

    // stage 1
    k_gray<<<(BATCH*10000 + 255)/256, 256>>>(x);
    k_rgbconv<<<1152, 256>>>(x, rgb_w);
    k_grayconv<<<1152, 256>>>(gray_w);
    run_select((unsigned*)ph1a, (const float*)pd1,  691200, 345600, w1, (float*)pthrA);
    run_select((unsigned*)ph1b, (const float*)pd1g, 230400, 115200, w1, (float*)pthrB);
    k_sfm1<<<(BATCH*230400 + 255)/256, 256>>>(w1);

    // conv1 (RBF, k=3, pad=1): (B,100,48,48) -> (B,225,48,48)
    k_im2col_stage<<<1536, 256, 63600>>>((const float*)pact2,
        (__nv_bfloat16*)pc1h, (__nv_bfloat16*)pc1l, (float*)ps2a,
        100, 48, 48, 48, 48, 1, 900, 960);
    k_wprep<<<(256*960 + 255)/256, 256>>>(conv1_w, (__nv_bfloat16*)pw1h, (__nv_bfloat16*)pw1l,
                                          225, 900, 256, 960);
    k_rowsq_hl<<<(256*32 + 255)/256, 256>>>((const __nv_bfloat16*)pw1h, (const __nv_bfloat16*)pw1l,
                                            (float*)pwsq1, 256, 960);
    k_gemm_mma<1><<<dim3(576, 1), 256, 196608>>>(
        (const __nv_bfloat16*)pw1h, (const __nv_bfloat16*)pw1l,
        (const __nv_bfloat16*)pc1h, (const __nv_bfloat16*)pc1l,
        (const float*)pwsq1, (const float*)ps2a, (float*)pd2,
        960, 15, 225, 73728, 2304, 225, (unsigned*)ph1a);
    run_select((unsigned*)ph1a, (const float*)pd2, 518400, 207360, w2, (float*)pthrA);
    k_sfm2<<<(BATCH*129600 + 255)/256, 256>>>(w2);

    // conv2 (RBF, k=3, pad=0): (B,225,24,24) -> (B,625,22,22)
    k_im2col_stage<<<704, 256, 81008>>>((const float*)pact3,
        (__nv_bfloat16*)pc2h, (__nv_bfloat16*)pc2l, (float*)ps2b,
        225, 24, 24, 22, 22, 0, 2025, 2048);
    k_wprep<<<(640*2048 + 255)/256, 256>>>(conv2_w, (__nv_bfloat16*)pw2h, (__nv_bfloat16*)pw2l,
                                           625, 2025, 640, 2048);
    k_rowsq_hl<<<(640*32 + 255)/256, 256>>>((const __nv_bfloat16*)pw2h, (const __nv_bfloat16*)pw2l,
                                            (float*)pwsq2, 640, 2048);
    k_gemm_mma<0><<<dim3(5, 61), 256, 196608>>>(
        (const __nv_bfloat16*)pc2h, (const __nv_bfloat16*)pc2l,
        (const __nv_bfloat16*)pw2h, (const __nv_bfloat16*)pw2l,
        (const float*)ps2b, (const float*)pwsq2, (float*)pd3,
        2048, 32, 15488, 625, 484, 625, (unsigned*)ph1a);
    run_select((unsigned*)ph1a, (const float*)pd3, 302500, 121000, w3, (float*)pthrA);

    // fused triangle + FC (chunked partials + deterministic finisher)
    k_fcpart<<<dim3(FC_CHUNKS, BATCH), 256>>>(fc_w, w3);
    k_fcfin<<<1, 320>>>(fc_b, out);
}

// round 12
// speedup vs baseline: 1.1077x; 1.0451x over previous
#include <cuda_runtime.h>
#include <cuda_bf16.h>
#include <math.h>
#include <stdint.h>

#define BATCH 32

// ---------------- persistent scratch (device globals; no allocation) ----------------
__device__ float g_gray[BATCH*10000];
__device__ float g_d1 [BATCH*691200];          // rgb distances  (B,75,96,96)
__device__ float g_d1g[BATCH*230400];          // gray distances (B,25,96,96)
__device__ float g_act2[BATCH*230400];         // after triangle+sfm (B,100,48,48)
__device__ float g_act3[BATCH*129600];         // after triangle+sfm (B,225,24,24)
__device__ float g_d2 [BATCH*518400];          // conv1 distances (B,225,48,48)
__device__ float g_d3 [BATCH*302500];          // conv2 distances (B,625,22,22)

// bf16 hi/lo split operands (padded; conv2 M padded 15488->15616 for 256-row tiles)
__device__ __align__(16) __nv_bfloat16 g_col1h[73728*960];
__device__ __align__(16) __nv_bfloat16 g_col1l[73728*960];
__device__ __align__(16) __nv_bfloat16 g_col2h[15616*2048];
__device__ __align__(16) __nv_bfloat16 g_col2l[15616*2048];
__device__ __align__(16) __nv_bfloat16 g_w1h[256*960];
__device__ __align__(16) __nv_bfloat16 g_w1l[256*960];
__device__ __align__(16) __nv_bfloat16 g_w2h[640*2048];
__device__ __align__(16) __nv_bfloat16 g_w2l[640*2048];
__device__ float g_s2a [73728];
__device__ float g_s2b [15616];
__device__ float g_wsq1[256];
__device__ float g_wsq2[640];

__device__ unsigned g_histo[64*2048];      // filtered-pass histos (zero-invariant); 64 slots for merged stage-1
__device__ unsigned g_h1a[BATCH*2048];     // pass-1 histo (producer-filled) A
__device__ unsigned g_h1b[BATCH*2048];     // pass-1 histo (producer-filled) B
__device__ unsigned g_prefix[64];
__device__ int      g_krem[64];
__device__ float    g_thrA[BATCH];
__device__ float    g_thrB[BATCH];

#define FC_CHUNKS 16
__device__ float g_fcpart[FC_CHUNKS*BATCH*10];

// ---------------- ptx helpers (plain sm_103-safe: no tcgen05) ----------------
__device__ __forceinline__ uint32_t smem_u32(const void* p) {
    uint32_t a;
    asm("{ .reg .u64 t; cvta.to.shared.u64 t, %1; cvt.u32.u64 %0, t; }" : "=r"(a) : "l"(p));
    return a;
}
__device__ __forceinline__ void cp16(uint32_t dst, const void* src) {
    asm volatile("cp.async.cg.shared.global [%0], [%1], 16;" :: "r"(dst), "l"(src));
}
#define CP_COMMIT() asm volatile("cp.async.commit_group;" ::: "memory")
#define CP_WAIT1()  asm volatile("cp.async.wait_group 1;" ::: "memory")
#define CP_WAIT0()  asm volatile("cp.async.wait_group 0;" ::: "memory")

__device__ __forceinline__ void ldm_x4(uint32_t* r, uint32_t addr) {
    asm volatile("ldmatrix.sync.aligned.m8n8.x4.shared.b16 {%0,%1,%2,%3}, [%4];"
                 : "=r"(r[0]), "=r"(r[1]), "=r"(r[2]), "=r"(r[3]) : "r"(addr));
}
__device__ __forceinline__ void mma_bf16(float* d, const uint32_t* a, const uint32_t* b) {
    asm volatile("mma.sync.aligned.m16n8k16.row.col.f32.bf16.bf16.f32 "
                 "{%0,%1,%2,%3}, {%4,%5,%6,%7}, {%8,%9}, {%0,%1,%2,%3};"
                 : "+f"(d[0]), "+f"(d[1]), "+f"(d[2]), "+f"(d[3])
                 : "r"(a[0]), "r"(a[1]), "r"(a[2]), "r"(a[3]), "r"(b[0]), "r"(b[1]));
}
#define SWZ128(x) ((x) ^ (((x) >> 3) & 0x70))

__device__ __forceinline__ float tri_val(float v, float thr, float invw) {
    return (v > thr) ? 0.0f : 1.0f - v * invw;
}

// ---------------- parallel k-th-bin search (256-thread block) ----------------
__device__ __forceinline__ unsigned block_kth(const unsigned* hist, int nbins, unsigned k,
                                              unsigned* scanbuf, int* sel_sm, unsigned* krem_sm,
                                              int tid) {
    int per = nbins >> 8;
    int base = tid * per;
    unsigned own = 0;
    for (int j = 0; j < per; j++) own += hist[base + j];
    scanbuf[tid] = own;
    __syncthreads();
    for (int off = 1; off < 256; off <<= 1) {
        unsigned v = (tid >= off) ? scanbuf[tid - off] : 0u;
        __syncthreads();
        scanbuf[tid] += v;
        __syncthreads();
    }
    unsigned incl = scanbuf[tid];
    unsigned excl = incl - own;
    if (excl < k && incl >= k) {
        unsigned c = excl;
        for (int j = 0; j < per; j++) {
            unsigned v = hist[base + j];
            if (c + v >= k) { *sel_sm = base + j; *krem_sm = k - c; break; }
            c += v;
        }
    }
    __syncthreads();
    return (unsigned)*sel_sm;
}

// ---------------- grayscale ----------------
__global__ void k_gray(const float* __restrict__ x) {
    int i = blockIdx.x * blockDim.x + threadIdx.x;
    if (i >= BATCH*10000) return;
    int b = i / 10000, p = i - b*10000;
    const float* xb = x + (size_t)b * 30000;
    g_gray[i] = 0.2989f*xb[p] + 0.587f*xb[10000+p] + 0.114f*xb[20000+p];
}

// ---------------- rgb conv (5x5) -> d1, with fused pass-1 histogram ----------------
__global__ void k_rgbconv(const float* __restrict__ x, const float* __restrict__ rgb_w) {
    __shared__ float sw[225];
    __shared__ float swsq[75];
    __shared__ unsigned hist[2048];
    int t = threadIdx.x;
    if (t < 225) sw[t] = rgb_w[t];
    for (int j = t; j < 2048; j += 256) hist[j] = 0u;
    __syncthreads();
    if (t < 75) {
        float a = sw[t*3], b2 = sw[t*3+1], c = sw[t*3+2];
        swsq[t] = a*a + b2*b2 + c*c;
    }
    __syncthreads();
    int i = blockIdx.x * 256 + t;
    int b = i / 9216, l = i - b*9216;
    int oy = l / 96, ox = l - oy*96;
    const float* xb = x + (size_t)b * 30000;
    float s1[3];
    float s2 = 0.f;
    #pragma unroll
    for (int c = 0; c < 3; c++) {
        float sc = 0.f;
        const float* xc = xb + c*10000;
        #pragma unroll
        for (int dy = 0; dy < 5; dy++) {
            const float* row = xc + (oy+dy)*100 + ox;
            #pragma unroll
            for (int dx = 0; dx < 5; dx++) { float v = row[dx]; sc += v; s2 += v*v; }
        }
        s1[c] = sc;
    }
    float* o = g_d1 + (size_t)b * 691200 + l;
    #pragma unroll 5
    for (int f = 0; f < 75; f++) {
        float d2 = s2 + 25.0f*swsq[f]
                 - 2.0f*(sw[f*3]*s1[0] + sw[f*3+1]*s1[1] + sw[f*3+2]*s1[2]);
        float d = sqrtf(fmaxf(d2, 0.0f));
        o[(size_t)f*9216] = d;
        atomicAdd(&hist[__float_as_uint(d) >> 21], 1u);
    }
    __syncthreads();
    int bb = blockIdx.x / 36;
    for (int j = t; j < 2048; j += 256)
        if (hist[j]) atomicAdd(&g_h1a[bb*2048 + j], hist[j]);
}

// ---------------- gray RBF conv (5x5) -> d1g, with fused pass-1 histogram ----------------
__global__ void k_grayconv(const float* __restrict__ gray_w) {
    __shared__ float sw[625];
    __shared__ float swsq[25];
    __shared__ unsigned hist[2048];
    int t = threadIdx.x;
    for (int j = t; j < 625; j += 256) sw[j] = gray_w[j];
    for (int j = t; j < 2048; j += 256) hist[j] = 0u;
    __syncthreads();
    if (t < 25) {
        float s = 0.f;
        for (int k = 0; k < 25; k++) { float v = sw[t*25+k]; s += v*v; }
        swsq[t] = s;
    }
    __syncthreads();
    int i = blockIdx.x * 256 + t;
    int b = i / 9216, l = i - b*9216;
    int oy = l / 96, ox = l - oy*96;
    const float* gb = g_gray + (size_t)b * 10000;
    float p[25];
    float pn = 0.f;
    #pragma unroll
    for (int dy = 0; dy < 5; dy++) {
        const float* row = gb + (oy+dy)*100 + ox;
        #pragma unroll
        for (int dx = 0; dx < 5; dx++) { float v = row[dx]; p[dy*5+dx] = v; pn += v*v; }
    }
    float* o = g_d1g + (size_t)b * 230400 + l;
    #pragma unroll 5
    for (int f = 0; f < 25; f++) {
        float dot = 0.f;
        #pragma unroll
        for (int k = 0; k < 25; k++) dot += sw[f*25+k] * p[k];
        float d = sqrtf(fmaxf(pn + swsq[f] - 2.0f*dot, 0.0f));
        o[(size_t)f*9216] = d;
        atomicAdd(&hist[__float_as_uint(d) >> 21], 1u);
    }
    __syncthreads();
    int bb = blockIdx.x / 36;
    for (int j = t; j < 2048; j += 256)
        if (hist[j]) atomicAdd(&g_h1b[bb*2048 + j], hist[j]);
}

// ---------------- single-select kernels (slots 0..31) ----------------
__global__ void k_scan1p(unsigned* __restrict__ h1, int kk) {
    __shared__ unsigned scanbuf[256];
    __shared__ int ssel;
    __shared__ unsigned skrem;
    int b = blockIdx.x, tid = threadIdx.x;
    unsigned* h = h1 + b*2048;
    unsigned sel = block_kth(h, 2048, (unsigned)kk, scanbuf, &ssel, &skrem, tid);
    if (tid == 0) { g_prefix[b] = sel << 21; g_krem[b] = (int)skrem; }
    __syncthreads();
    for (int j = tid; j < 2048; j += 256) h[j] = 0u;
}

__global__ void k_hist(const float* __restrict__ data, int Nper, int shift, int nbins, int hichk) {
    __shared__ unsigned sh[2048];
    int t = threadIdx.x;
    for (int j = t; j < nbins; j += blockDim.x) sh[j] = 0u;
    __syncthreads();
    int b = blockIdx.y;
    unsigned want = g_prefix[b] >> hichk;
    const uint4* p = (const uint4*)(data + (size_t)b * Nper);
    unsigned mask = (unsigned)nbins - 1u;
    int n4 = Nper >> 2;
    for (int i = blockIdx.x * blockDim.x + t; i < n4; i += gridDim.x * blockDim.x) {
        uint4 u = p[i];
        if ((u.x >> hichk) == want) atomicAdd(&sh[(u.x >> shift) & mask], 1u);
        if ((u.y >> hichk) == want) atomicAdd(&sh[(u.y >> shift) & mask], 1u);
        if ((u.z >> hichk) == want) atomicAdd(&sh[(u.z >> shift) & mask], 1u);
        if ((u.w >> hichk) == want) atomicAdd(&sh[(u.w >> shift) & mask], 1u);
    }
    __syncthreads();
    for (int j = t; j < nbins; j += blockDim.x)
        if (sh[j]) atomicAdd(&g_histo[b*2048+j], sh[j]);
}

__global__ void k_scanp(int nbins, int shift, int finalize, const float* wptr, float* thrOut) {
    __shared__ unsigned scanbuf[256];
    __shared__ int ssel;
    __shared__ unsigned skrem;
    int b = blockIdx.x, tid = threadIdx.x;
    unsigned* h = &g_histo[b*2048];
    unsigned sel = block_kth(h, nbins, (unsigned)g_krem[b], scanbuf, &ssel, &skrem, tid);
    if (tid == 0) {
        g_prefix[b] |= sel << shift;
        g_krem[b] = (int)skrem;
        if (finalize) thrOut[b] = fminf(__uint_as_float(g_prefix[b]), wptr[0]);
    }
    __syncthreads();
    for (int j = tid; j < 2048; j += 256) h[j] = 0u;
}

// ---------------- merged stage-1 selects (slots 0..31 = A, 32..63 = B) ----------------
__global__ void k_scan1m(int kkA, int kkB) {
    __shared__ unsigned scanbuf[256];
    __shared__ int ssel;
    __shared__ unsigned skrem;
    int b = blockIdx.x, tid = threadIdx.x;
    unsigned* h = (b < 32) ? &g_h1a[b*2048] : &g_h1b[(b-32)*2048];
    unsigned kk = (b < 32) ? (unsigned)kkA : (unsigned)kkB;
    unsigned sel = block_kth(h, 2048, kk, scanbuf, &ssel, &skrem, tid);
    if (tid == 0) { g_prefix[b] = sel << 21; g_krem[b] = (int)skrem; }
    __syncthreads();
    for (int j = tid; j < 2048; j += 256) h[j] = 0u;
}

__global__ void k_histm(const float* __restrict__ dA, const float* __restrict__ dB,
                        int shift, int nbins, int hichk) {
    __shared__ unsigned sh[2048];
    int t = threadIdx.x;
    for (int j = t; j < nbins; j += blockDim.x) sh[j] = 0u;
    __syncthreads();
    int yy = blockIdx.y;
    bool isA = yy < 32;
    int b = isA ? yy : yy - 32;
    int Nper = isA ? 691200 : 230400;
    const uint4* p = (const uint4*)((isA ? dA + (size_t)b*691200 : dB + (size_t)b*230400));
    unsigned want = g_prefix[yy] >> hichk;
    unsigned mask = (unsigned)nbins - 1u;
    int n4 = Nper >> 2;
    for (int i = blockIdx.x * blockDim.x + t; i < n4; i += gridDim.x * blockDim.x) {
        uint4 u = p[i];
        if ((u.x >> hichk) == want) atomicAdd(&sh[(u.x >> shift) & mask], 1u);
        if ((u.y >> hichk) == want) atomicAdd(&sh[(u.y >> shift) & mask], 1u);
        if ((u.z >> hichk) == want) atomicAdd(&sh[(u.z >> shift) & mask], 1u);
        if ((u.w >> hichk) == want) atomicAdd(&sh[(u.w >> shift) & mask], 1u);
    }
    __syncthreads();
    for (int j = t; j < nbins; j += blockDim.x)
        if (sh[j]) atomicAdd(&g_histo[yy*2048+j], sh[j]);
}

__global__ void k_scanm(int nbins, int shift, int finalize, const float* wptr) {
    __shared__ unsigned scanbuf[256];
    __shared__ int ssel;
    __shared__ unsigned skrem;
    int b = blockIdx.x, tid = threadIdx.x;
    unsigned* h = &g_histo[b*2048];
    unsigned sel = block_kth(h, nbins, (unsigned)g_krem[b], scanbuf, &ssel, &skrem, tid);
    if (tid == 0) {
        g_prefix[b] |= sel << shift;
        g_krem[b] = (int)skrem;
        if (finalize) {
            float thr = fminf(__uint_as_float(g_prefix[b]), wptr[0]);
            if (b < 32) g_thrA[b] = thr; else g_thrB[b-32] = thr;
        }
    }
    __syncthreads();
    for (int j = tid; j < 2048; j += 256) h[j] = 0u;
}

// ---------------- fused triangle + sfm (stage 1) ----------------
__global__ void k_sfm1(const float* __restrict__ w1) {
    int i = blockIdx.x * blockDim.x + threadIdx.x;
    if (i >= BATCH*230400) return;
    int b = i / 230400;
    int r = i - b*230400;
    int c = r / 2304;
    int l = r - c*2304;
    int oy = l / 48, ox = l - oy*48;
    float thr;
    const float* src;
    if (c < 75) { thr = g_thrA[b]; src = g_d1  + (size_t)b*691200 + (size_t)c*9216; }
    else        { thr = g_thrB[b]; src = g_d1g + (size_t)b*230400 + (size_t)(c-75)*9216; }
    float invw = 1.0f / w1[0];
    int y = 2*oy, x2 = 2*ox;
    float v00 = tri_val(src[y*96 + x2],       thr, invw);
    float v01 = tri_val(src[y*96 + x2 + 1],   thr, invw);
    float v10 = tri_val(src[(y+1)*96 + x2],   thr, invw);
    float v11 = tri_val(src[(y+1)*96 + x2+1], thr, invw);
    g_act2[i] = 0.25f * (0.90f*v00 + 0.93f*v01 + 0.96f*v10 + 0.99f*v11);
}

// ---------------- fused triangle + sfm (stage 2) ----------------
__global__ void k_sfm2(const float* __restrict__ w2) {
    int i = blockIdx.x * blockDim.x + threadIdx.x;
    if (i >= BATCH*129600) return;
    int b = i / 129600;
    int r = i - b*129600;
    int c = r / 576;
    int l = r - c*576;
    int oy = l / 24, ox = l - oy*24;
    float thr = g_thrA[b];
    float invw = 1.0f / w2[0];
    const float* src = g_d2 + ((size_t)b*225 + c) * 2304;
    int y = 2*oy, x2 = 2*ox;
    float v00 = tri_val(src[y*48 + x2],       thr, invw);
    float v01 = tri_val(src[y*48 + x2 + 1],   thr, invw);
    float v10 = tri_val(src[(y+1)*48 + x2],   thr, invw);
    float v11 = tri_val(src[(y+1)*48 + x2+1], thr, invw);
    g_act3[i] = 0.25f * (0.90f*v00 + 0.93f*v01 + 0.96f*v10 + 0.99f*v11);
}

// ---------------- staged-smem im2col -> bf16 hi/lo + row s2 ----------------
__global__ void __launch_bounds__(256) k_im2col_stage(
    const float* __restrict__ in,
    __nv_bfloat16* __restrict__ outh, __nv_bfloat16* __restrict__ outl,
    float* __restrict__ s2out,
    int C, int Hin, int Win, int oh, int ow, int pad, int Ktrue, int Kpad)
{
    extern __shared__ char smraw[];
    float* sm = (float*)smraw;
    int W2 = Win + 2*pad;
    int stageN = C * 3 * W2;
    int* kcol = (int*)(smraw + (size_t)stageN * 4);

    int bid = blockIdx.x;
    int b = bid / oh, oy = bid - b*oh;
    int tid = threadIdx.x;

    for (int k = tid; k < Ktrue; k += 256) {
        int c = k / 9; int r = k - c*9; int di = r / 3; int dj = r - di*3;
        kcol[k] = (c*3 + di)*W2 + dj;
    }
    const float* inb = in + (size_t)b * C * Hin * Win;
    for (int idx = tid; idx < stageN; idx += 256) {
        int c = idx / (3*W2); int rem = idx - c*3*W2;
        int dy = rem / W2; int xx = rem - dy*W2;
        int iy = oy + dy - pad; int ix = xx - pad;
        float v = 0.f;
        if (iy >= 0 && iy < Hin && ix >= 0 && ix < Win)
            v = inb[((size_t)c*Hin + iy)*Win + ix];
        sm[idx] = v;
    }
    __syncthreads();

    int L = oh * ow;
    int mbase = b*L + oy*ow;
    int KH = Kpad >> 1;
    int total = ow * KH;
    int ox = tid / KH, p = tid - ox*KH;
    for (int j = tid; j < total; j += 256) {
        int k0 = p*2, k1 = k0 + 1;
        float v0 = (k0 < Ktrue) ? sm[kcol[k0] + ox] : 0.f;
        float v1 = (k1 < Ktrue) ? sm[kcol[k1] + ox] : 0.f;
        __nv_bfloat16 h0 = __float2bfloat16(v0);
        __nv_bfloat16 h1 = __float2bfloat16(v1);
        __nv_bfloat16 l0 = __float2bfloat16(v0 - __bfloat162float(h0));
        __nv_bfloat16 l1 = __float2bfloat16(v1 - __bfloat162float(h1));
        size_t off = (size_t)(mbase + ox) * Kpad + k0;
        *(__nv_bfloat162*)(outh + off) = __nv_bfloat162(h0, h1);
        *(__nv_bfloat162*)(outl + off) = __nv_bfloat162(l0, l1);
        p += 256;
        if (p >= KH) { p -= KH; ox++; }
    }

    int wid = tid >> 5, lane = tid & 31;
    for (int oxx = wid; oxx < ow; oxx += 8) {
        float s = 0.f;
        for (int k = lane; k < Ktrue; k += 32) {
            float v = sm[kcol[k] + oxx];
            __nv_bfloat16 h = __float2bfloat16(v);
            float fh = __bfloat162float(h);
            __nv_bfloat16 lo = __float2bfloat16(v - fh);
            float rec = fh + __bfloat162float(lo);
            s += rec*rec;
        }
        #pragma unroll
        for (int o2 = 16; o2 > 0; o2 >>= 1) s += __shfl_down_sync(0xFFFFFFFFu, s, o2);
        if (lane == 0) s2out[mbase + oxx] = s;
    }
}

// ---------------- weight prep: pad + bf16 split ----------------
__global__ void k_wprep(const float* __restrict__ w,
                        __nv_bfloat16* __restrict__ outh, __nv_bfloat16* __restrict__ outl,
                        int N, int K, int Npad, int Kpad) {
    int i = blockIdx.x * blockDim.x + threadIdx.x;
    if (i >= Npad*Kpad) return;
    int n = i / Kpad, k = i - n*Kpad;
    float v = (n < N && k < K) ? w[(size_t)n*K + k] : 0.f;
    __nv_bfloat16 h = __float2bfloat16(v);
    outh[i] = h;
    outl[i] = __float2bfloat16(v - __bfloat162float(h));
}

__global__ void k_rowsq_hl(const __nv_bfloat16* __restrict__ H, const __nv_bfloat16* __restrict__ Lo,
                           float* __restrict__ out, int rows, int Kp) {
    int w = (blockIdx.x * blockDim.x + threadIdx.x) >> 5;
    int lane = threadIdx.x & 31;
    if (w >= rows) return;
    const __nv_bfloat162* h2 = (const __nv_bfloat162*)(H  + (size_t)w * Kp);
    const __nv_bfloat162* l2 = (const __nv_bfloat162*)(Lo + (size_t)w * Kp);
    int K2 = Kp >> 1;
    float s = 0.f;
    for (int k = lane; k < K2; k += 32) {
        __nv_bfloat162 a = h2[k], b = l2[k];
        float v0 = __bfloat162float(a.x) + __bfloat162float(b.x);
        float v1 = __bfloat162float(a.y) + __bfloat162float(b.y);
        s += v0*v0 + v1*v1;
    }
    #pragma unroll
    for (int off = 16; off > 0; off >>= 1) s += __shfl_down_sync(0xFFFFFFFFu, s, off);
    if (lane == 0) out[w] = s;
}

// ---------------- HMMA bf16x3 GEMM with RBF epilogue + fused pass-1 histogram ----------------
// CTA tile 256(m) x (NFR*16)(n), 8 warps 4m x 2n, warp tile 64 x NFR*8.
#define A_TILE  32768

__device__ __forceinline__ void prefetch_rows(uint32_t sdst, const __nv_bfloat16* __restrict__ src,
                                              int row0, int Kpad, int k0, int tid, int nrows) {
    for (int i = tid; i < nrows*8; i += 256) {
        int row = i >> 3, c8 = i & 7;
        cp16(sdst + SWZ128(row*128 + c8*16),
             src + (size_t)(row0 + row) * Kpad + k0 + c8*8);
    }
}

template<int MODE, int NFR>
__global__ void __launch_bounds__(256, 1)
k_gemm_mma(const __nv_bfloat16* __restrict__ Ah, const __nv_bfloat16* __restrict__ Al,
           const __nv_bfloat16* __restrict__ Wh, const __nv_bfloat16* __restrict__ Wl,
           const float* __restrict__ s2m, const float* __restrict__ s2n,
           float* __restrict__ out, int Kpad, int NC, int Mlim, int Nlim, int L, int NW,
           unsigned* __restrict__ h1)
{
    constexpr int NT = NFR * 16;            // CTA n-tile
    constexpr int W_TILE = NT * 128;        // bytes per W tile (hi or lo)
    constexpr int BUF = 2*A_TILE + 2*W_TILE;

    extern __shared__ char dsm[];
    const int tid  = threadIdx.x;
    const int wid  = tid >> 5;
    const int lane = tid & 31;
    const int m0 = blockIdx.y * 256;
    const int n0 = blockIdx.x * NT;
    const int m_w = (wid >> 1) * 64;
    const int n_w = (wid & 1) * (NFR*8);

    uint32_t sbase = smem_u32(dsm);

    float acc[4][NFR][4];
    #pragma unroll
    for (int a = 0; a < 4; a++)
        #pragma unroll
        for (int b = 0; b < NFR; b++)
            #pragma unroll
            for (int c = 0; c < 4; c++) acc[a][b][c] = 0.f;

    const int g  = lane >> 3;
    const int rr = lane & 7;
    const int a_row  = m_w + (g & 1)*8 + rr;
    const int a_colg = (g >> 1) * 16;
    const int b_row  = n_w + (g >> 1)*8 + rr;
    const int b_colg = (g & 1) * 16;

    prefetch_rows(sbase,                    Ah, m0, Kpad, 0, tid, 256);
    prefetch_rows(sbase + A_TILE,           Al, m0, Kpad, 0, tid, 256);
    prefetch_rows(sbase + 2*A_TILE,         Wh, n0, Kpad, 0, tid, NT);
    prefetch_rows(sbase + 2*A_TILE+W_TILE,  Wl, n0, Kpad, 0, tid, NT);
    CP_COMMIT();

    for (int ch = 0; ch < NC; ch++) {
        if (ch + 1 < NC) {
            uint32_t nb = sbase + ((ch+1) & 1) * BUF;
            int k0 = (ch+1) * 64;
            prefetch_rows(nb,                   Ah, m0, Kpad, k0, tid, 256);
            prefetch_rows(nb + A_TILE,          Al, m0, Kpad, k0, tid, 256);
            prefetch_rows(nb + 2*A_TILE,        Wh, n0, Kpad, k0, tid, NT);
            prefetch_rows(nb + 2*A_TILE+W_TILE, Wl, n0, Kpad, k0, tid, NT);
            CP_COMMIT();
            CP_WAIT1();
        } else {
            CP_WAIT0();
        }
        __syncthreads();

        uint32_t buf = sbase + (ch & 1) * BUF;
        uint32_t tAh = buf, tAl = buf + A_TILE;
        uint32_t tWh = buf + 2*A_TILE, tWl = buf + 2*A_TILE + W_TILE;

        #pragma unroll
        for (int ks = 0; ks < 4; ks++) {
            int acol = ks*32 + a_colg;
            int bcol = ks*32 + b_colg;
            uint32_t ah[4][4], al[4][4];
            #pragma unroll
            for (int mf = 0; mf < 4; mf++) {
                uint32_t off = SWZ128((a_row + mf*16)*128 + acol);
                ldm_x4(ah[mf], tAh + off);
                ldm_x4(al[mf], tAl + off);
            }
            #pragma unroll
            for (int q = 0; q < NFR/2; q++) {
                uint32_t off = SWZ128((b_row + q*16)*128 + bcol);
                uint32_t bh[4], bl[4];
                ldm_x4(bh, tWh + off);
                ldm_x4(bl, tWl + off);
                #pragma unroll
                for (int mf = 0; mf < 4; mf++)
                    #pragma unroll
                    for (int hlf = 0; hlf < 2; hlf++) {
                        int nf = q*2 + hlf;
                        mma_bf16(acc[mf][nf], ah[mf], &bh[hlf*2]);
                        mma_bf16(acc[mf][nf], ah[mf], &bl[hlf*2]);
                        mma_bf16(acc[mf][nf], al[mf], &bh[hlf*2]);
                    }
            }
        }
        __syncthreads();
    }

    unsigned* sh = (unsigned*)dsm;
    for (int i = tid; i < 4096; i += 256) sh[i] = 0u;
    __syncthreads();

    const int b_base = (MODE ? n0 : m0) / L;
    const int tg = lane >> 2, tk = lane & 3;
    #pragma unroll
    for (int mf = 0; mf < 4; mf++) {
        #pragma unroll
        for (int h = 0; h < 2; h++) {
            int m = m0 + m_w + mf*16 + tg + h*8;
            if (m >= Mlim) continue;
            float smv = s2m[m];
            if (MODE == 0) {
                int b = m / L;
                int l = m - b*L;
                float* ob = out + ((size_t)b*NW)*L + l;
                int slot = (b - b_base) << 11;
                #pragma unroll
                for (int nf = 0; nf < NFR; nf++) {
                    #pragma unroll
                    for (int j = 0; j < 2; j++) {
                        int n = n0 + n_w + nf*8 + tk*2 + j;
                        if (n >= Nlim) continue;
                        float d2v = smv + s2n[n] - 2.0f * acc[mf][nf][h*2 + j];
                        float d = sqrtf(fmaxf(d2v, 0.0f));
                        ob[(size_t)n * L] = d;
                        atomicAdd(&sh[slot | (__float_as_uint(d) >> 21)], 1u);
                    }
                }
            } else {
                #pragma unroll
                for (int nf = 0; nf < NFR; nf++) {
                    #pragma unroll
                    for (int j = 0; j < 2; j++) {
                        int n = n0 + n_w + nf*8 + tk*2 + j;
                        if (n >= Nlim) continue;
                        int b = n / L;
                        int l = n - b*L;
                        float d2v = smv + s2n[n] - 2.0f * acc[mf][nf][h*2 + j];
                        float d = sqrtf(fmaxf(d2v, 0.0f));
                        out[((size_t)b*NW + m)*L + l] = d;
                        atomicAdd(&sh[((b - b_base) << 11) | (__float_as_uint(d) >> 21)], 1u);
                    }
                }
            }
        }
    }
    __syncthreads();
    for (int i = tid; i < 4096; i += 256) {
        unsigned v = sh[i];
        int bb = b_base + (i >> 11);
        if (v && bb < BATCH) atomicAdd(&h1[bb*2048 + (i & 2047)], v);
    }
}

// ---------------- fused triangle + FC: chunked partials (deterministic) ----------------
#define FC_CHUNK_LEN 4727   // ceil(75625/16)
__global__ void __launch_bounds__(256) k_fcpart(const float* __restrict__ fcw,
                                                const float* __restrict__ w3) {
    int chunk = blockIdx.x, b = blockIdx.y;
    int k0 = chunk * FC_CHUNK_LEN;
    int k1 = k0 + FC_CHUNK_LEN; if (k1 > 75625) k1 = 75625;
    float thr = g_thrA[b];
    float invw = 1.0f / w3[0];
    const float4* src = (const float4*)(g_d3 + (size_t)b * 302500);
    float acc[10];
    #pragma unroll
    for (int n = 0; n < 10; n++) acc[n] = 0.f;
    for (int k = k0 + threadIdx.x; k < k1; k += 256) {
        float4 v = src[k];
        float t0 = (v.x > thr ? 0.f : 1.f - v.x*invw);
        float t1 = (v.y > thr ? 0.f : 1.f - v.y*invw);
        float t2 = (v.z > thr ? 0.f : 1.f - v.z*invw);
        float t3 = (v.w > thr ? 0.f : 1.f - v.w*invw);
        #pragma unroll
        for (int n = 0; n < 10; n++) {
            float4 w = ((const float4*)(fcw + (size_t)n * 302500))[k];
            acc[n] += t0*w.x + t1*w.y + t2*w.z + t3*w.w;
        }
    }
    __shared__ float red[256];
    #pragma unroll
    for (int n = 0; n < 10; n++) {
        red[threadIdx.x] = acc[n];
        __syncthreads();
        for (int st = 128; st > 0; st >>= 1) {
            if (threadIdx.x < st) red[threadIdx.x] += red[threadIdx.x + st];
            __syncthreads();
        }
        if (threadIdx.x == 0) g_fcpart[((size_t)chunk*BATCH + b)*10 + n] = red[0];
        __syncthreads();
    }
}

__global__ void k_fcfin(const float* __restrict__ fcb, float* __restrict__ out) {
    int i = threadIdx.x;
    if (i >= BATCH*10) return;
    int n = i % 10;
    float s = fcb[n];
    for (int c = 0; c < FC_CHUNKS; c++) s += g_fcpart[(size_t)c*BATCH*10 + i];
    out[i] = s;
}

// ---------------- host side ----------------
static void run_select(unsigned* h1, const float* data, int Nper, int kk,
                       const float* wptr, float* thrOut) {
    k_scan1p<<<BATCH, 256>>>(h1, kk);
    k_hist<<<dim3(64, BATCH), 256>>>(data, Nper, 10, 2048, 21);
    k_scanp<<<BATCH, 256>>>(2048, 10, 0, nullptr, nullptr);
    k_hist<<<dim3(64, BATCH), 256>>>(data, Nper, 0, 1024, 10);
    k_scanp<<<BATCH, 256>>>(1024, 0, 1, wptr, thrOut);
}

extern "C" void kernel_launch(void* const* d_in, const int* in_sizes, int n_in,
                              void* d_out, int out_size) {
    const float* x       = (const float*)d_in[0];
    const float* rgb_w   = (const float*)d_in[1];
    const float* gray_w  = (const float*)d_in[2];
    const float* conv1_w = (const float*)d_in[3];
    const float* conv2_w = (const float*)d_in[4];
    const float* fc_w    = (const float*)d_in[5];
    const float* fc_b    = (const float*)d_in[6];
    const float* w1      = (const float*)d_in[7];
    const float* w2      = (const float*)d_in[8];
    const float* w3      = (const float*)d_in[9];
    float* out = (float*)d_out;

    void *pd1, *pd1g, *pact2, *pact3, *pd2, *pd3, *pthrA, *pthrB;
    void *pc1h, *pc1l, *pc2h, *pc2l, *pw1h, *pw1l, *pw2h, *pw2l;
    void *ps2a, *ps2b, *pwsq1, *pwsq2, *ph1a, *ph1b;
    cudaGetSymbolAddress(&pd1,   g_d1);
    cudaGetSymbolAddress(&pd1g,  g_d1g);
    cudaGetSymbolAddress(&pact2, g_act2);
    cudaGetSymbolAddress(&pact3, g_act3);
    cudaGetSymbolAddress(&pd2,   g_d2);
    cudaGetSymbolAddress(&pd3,   g_d3);
    cudaGetSymbolAddress(&pthrA, g_thrA);
    cudaGetSymbolAddress(&pthrB, g_thrB);
    cudaGetSymbolAddress(&pc1h,  g_col1h);
    cudaGetSymbolAddress(&pc1l,  g_col1l);
    cudaGetSymbolAddress(&pc2h,  g_col2h);
    cudaGetSymbolAddress(&pc2l,  g_col2l);
    cudaGetSymbolAddress(&pw1h,  g_w1h);
    cudaGetSymbolAddress(&pw1l,  g_w1l);
    cudaGetSymbolAddress(&pw2h,  g_w2h);
    cudaGetSymbolAddress(&pw2l,  g_w2l);
    cudaGetSymbolAddress(&ps2a,  g_s2a);
    cudaGetSymbolAddress(&ps2b,  g_s2b);
    cudaGetSymbolAddress(&pwsq1, g_wsq1);
    cudaGetSymbolAddress(&pwsq2, g_wsq2);
    cudaGetSymbolAddress(&ph1a,  g_h1a);
    cudaGetSymbolAddress(&ph1b,  g_h1b);

    cudaFuncSetAttribute((const void*)k_gemm_mma<1,8>,  cudaFuncAttributeMaxDynamicSharedMemorySize, 196608);
    cudaFuncSetAttribute((const void*)k_gemm_mma<0,10>, cudaFuncAttributeMaxDynamicSharedMemorySize, 212992);
    cudaFuncSetAttribute(k_im2col_stage, cudaFuncAttributeMaxDynamicSharedMemorySize, 81008);

    // stage 1
    k_gray<<<(BATCH*10000 + 255)/256, 256>>>(x);
    k_rgbconv<<<1152, 256>>>(x, rgb_w);
    k_grayconv<<<1152, 256>>>(gray_w);
    // merged stage-1 selects (A: d1, B: d1g)
    k_scan1m<<<64, 256>>>(345600, 115200);
    k_histm<<<dim3(64, 64), 256>>>((const float*)pd1, (const float*)pd1g, 10, 2048, 21);
    k_scanm<<<64, 256>>>(2048, 10, 0, w1);
    k_histm<<<dim3(64, 64), 256>>>((const float*)pd1, (const float*)pd1g, 0, 1024, 10);
    k_scanm<<<64, 256>>>(1024, 0, 1, w1);
    k_sfm1<<<(BATCH*230400 + 255)/256, 256>>>(w1);

    // conv1 (RBF, k=3, pad=1): (B,100,48,48) -> (B,225,48,48)
    k_im2col_stage<<<1536, 256, 63600>>>((const float*)pact2,
        (__nv_bfloat16*)pc1h, (__nv_bfloat16*)pc1l, (float*)ps2a,
        100, 48, 48, 48, 48, 1, 900, 960);
    k_wprep<<<(256*960 + 255)/256, 256>>>(conv1_w, (__nv_bfloat16*)pw1h, (__nv_bfloat16*)pw1l,
                                          225, 900, 256, 960);
    k_rowsq_hl<<<(256*32 + 255)/256, 256>>>((const __nv_bfloat16*)pw1h, (const __nv_bfloat16*)pw1l,
                                            (float*)pwsq1, 256, 960);
    k_gemm_mma<1,8><<<dim3(576, 1), 256, 196608>>>(
        (const __nv_bfloat16*)pw1h, (const __nv_bfloat16*)pw1l,
        (const __nv_bfloat16*)pc1h, (const __nv_bfloat16*)pc1l,
        (const float*)pwsq1, (const float*)ps2a, (float*)pd2,
        960, 15, 225, 73728, 2304, 225, (unsigned*)ph1a);
    run_select((unsigned*)ph1a, (const float*)pd2, 518400, 207360, w2, (float*)pthrA);
    k_sfm2<<<(BATCH*129600 + 255)/256, 256>>>(w2);

    // conv2 (RBF, k=3, pad=0): (B,225,24,24) -> (B,625,22,22), N-tile 160 (4 n-blocks, 244 CTAs = 2 waves)
    k_im2col_stage<<<704, 256, 81008>>>((const float*)pact3,
        (__nv_bfloat16*)pc2h, (__nv_bfloat16*)pc2l, (float*)ps2b,
        225, 24, 24, 22, 22, 0, 2025, 2048);
    k_wprep<<<(640*2048 + 255)/256, 256>>>(conv2_w, (__nv_bfloat16*)pw2h, (__nv_bfloat16*)pw2l,
                                           625, 2025, 640, 2048);
    k_rowsq_hl<<<(640*32 + 255)/256, 256>>>((const __nv_bfloat16*)pw2h, (const __nv_bfloat16*)pw2l,
                                            (float*)pwsq2, 640, 2048);
    k_gemm_mma<0,10><<<dim3(4, 61), 256, 212992>>>(
        (const __nv_bfloat16*)pc2h, (const __nv_bfloat16*)pc2l,
        (const __nv_bfloat16*)pw2h, (const __nv_bfloat16*)pw2l,
        (const float*)ps2b, (const float*)pwsq2, (float*)pd3,
        2048, 32, 15488, 625, 484, 625, (unsigned*)ph1a);
    run_select((unsigned*)ph1a, (const float*)pd3, 302500, 121000, w3, (float*)pthrA);

    // fused triangle + FC (chunked partials + deterministic finisher)
    k_fcpart<<<dim3(FC_CHUNKS, BATCH), 256>>>(fc_w, w3);
    k_fcfin<<<1, 320>>>(fc_b, out);
}

// round 14
// speedup vs baseline: 1.4324x; 1.2931x over previous
#include <cuda_runtime.h>
#include <cuda_bf16.h>
#include <math.h>
#include <stdint.h>

#define BATCH 32

// ---------------- persistent scratch (device globals; no allocation) ----------------
__device__ float g_gray[BATCH*10000];
__device__ float g_d1 [BATCH*691200];
__device__ float g_d1g[BATCH*230400];
__device__ float g_act2[BATCH*230400];
__device__ float g_act3[BATCH*129600];
__device__ float g_d2 [BATCH*518400];
__device__ float g_d3 [BATCH*302500];

// operands: im2col side stored as SINGLE bf16 (rounded); weight side hi/lo split
__device__ __align__(16) __nv_bfloat16 g_col1h[73728*960];
__device__ __align__(16) __nv_bfloat16 g_col2h[15616*2048];
__device__ __align__(16) __nv_bfloat16 g_w1h[256*960];
__device__ __align__(16) __nv_bfloat16 g_w1l[256*960];
__device__ __align__(16) __nv_bfloat16 g_w2h[640*2048];
__device__ __align__(16) __nv_bfloat16 g_w2l[640*2048];
__device__ float g_s2a [73728];
__device__ float g_s2b [15616];
__device__ float g_wsq1[256];
__device__ float g_wsq2[640];

__device__ unsigned g_histo[64*2048];
__device__ unsigned g_h1a[BATCH*2048];
__device__ unsigned g_h1b[BATCH*2048];
__device__ unsigned g_prefix[64];
__device__ int      g_krem[64];
__device__ float    g_thrA[BATCH];
__device__ float    g_thrB[BATCH];

#define FC_CHUNKS 16
__device__ float g_fcpart[FC_CHUNKS*BATCH*10];

// ---------------- ptx helpers ----------------
__device__ __forceinline__ uint32_t smem_u32(const void* p) {
    uint32_t a;
    asm("{ .reg .u64 t; cvta.to.shared.u64 t, %1; cvt.u32.u64 %0, t; }" : "=r"(a) : "l"(p));
    return a;
}
__device__ __forceinline__ void cp16(uint32_t dst, const void* src) {
    asm volatile("cp.async.cg.shared.global [%0], [%1], 16;" :: "r"(dst), "l"(src));
}
#define CP_COMMIT() asm volatile("cp.async.commit_group;" ::: "memory")
#define CP_WAIT1()  asm volatile("cp.async.wait_group 1;" ::: "memory")
#define CP_WAIT0()  asm volatile("cp.async.wait_group 0;" ::: "memory")

__device__ __forceinline__ void ldm_x4(uint32_t* r, uint32_t addr) {
    asm volatile("ldmatrix.sync.aligned.m8n8.x4.shared.b16 {%0,%1,%2,%3}, [%4];"
                 : "=r"(r[0]), "=r"(r[1]), "=r"(r[2]), "=r"(r[3]) : "r"(addr));
}
__device__ __forceinline__ void mma_bf16(float* d, const uint32_t* a, const uint32_t* b) {
    asm volatile("mma.sync.aligned.m16n8k16.row.col.f32.bf16.bf16.f32 "
                 "{%0,%1,%2,%3}, {%4,%5,%6,%7}, {%8,%9}, {%0,%1,%2,%3};"
                 : "+f"(d[0]), "+f"(d[1]), "+f"(d[2]), "+f"(d[3])
                 : "r"(a[0]), "r"(a[1]), "r"(a[2]), "r"(a[3]), "r"(b[0]), "r"(b[1]));
}
#define SWZ128(x) ((x) ^ (((x) >> 3) & 0x70))

__device__ __forceinline__ float tri_val(float v, float thr, float invw) {
    return (v > thr) ? 0.0f : 1.0f - v * invw;
}

// ---------------- parallel k-th-bin search ----------------
__device__ __forceinline__ unsigned block_kth(const unsigned* hist, int nbins, unsigned k,
                                              unsigned* scanbuf, int* sel_sm, unsigned* krem_sm,
                                              int tid) {
    int per = nbins >> 8;
    int base = tid * per;
    unsigned own = 0;
    for (int j = 0; j < per; j++) own += hist[base + j];
    scanbuf[tid] = own;
    __syncthreads();
    for (int off = 1; off < 256; off <<= 1) {
        unsigned v = (tid >= off) ? scanbuf[tid - off] : 0u;
        __syncthreads();
        scanbuf[tid] += v;
        __syncthreads();
    }
    unsigned incl = scanbuf[tid];
    unsigned excl = incl - own;
    if (excl < k && incl >= k) {
        unsigned c = excl;
        for (int j = 0; j < per; j++) {
            unsigned v = hist[base + j];
            if (c + v >= k) { *sel_sm = base + j; *krem_sm = k - c; break; }
            c += v;
        }
    }
    __syncthreads();
    return (unsigned)*sel_sm;
}

// ---------------- grayscale ----------------
__global__ void k_gray(const float* __restrict__ x) {
    int i = blockIdx.x * blockDim.x + threadIdx.x;
    if (i >= BATCH*10000) return;
    int b = i / 10000, p = i - b*10000;
    const float* xb = x + (size_t)b * 30000;
    g_gray[i] = 0.2989f*xb[p] + 0.587f*xb[10000+p] + 0.114f*xb[20000+p];
}

// ---------------- rgb conv (5x5) -> d1, fused pass-1 histogram ----------------
__global__ void k_rgbconv(const float* __restrict__ x, const float* __restrict__ rgb_w) {
    __shared__ float sw[225];
    __shared__ float swsq[75];
    __shared__ unsigned hist[2048];
    int t = threadIdx.x;
    if (t < 225) sw[t] = rgb_w[t];
    for (int j = t; j < 2048; j += 256) hist[j] = 0u;
    __syncthreads();
    if (t < 75) {
        float a = sw[t*3], b2 = sw[t*3+1], c = sw[t*3+2];
        swsq[t] = a*a + b2*b2 + c*c;
    }
    __syncthreads();
    int i = blockIdx.x * 256 + t;
    int b = i / 9216, l = i - b*9216;
    int oy = l / 96, ox = l - oy*96;
    const float* xb = x + (size_t)b * 30000;
    float s1[3];
    float s2 = 0.f;
    #pragma unroll
    for (int c = 0; c < 3; c++) {
        float sc = 0.f;
        const float* xc = xb + c*10000;
        #pragma unroll
        for (int dy = 0; dy < 5; dy++) {
            const float* row = xc + (oy+dy)*100 + ox;
            #pragma unroll
            for (int dx = 0; dx < 5; dx++) { float v = row[dx]; sc += v; s2 += v*v; }
        }
        s1[c] = sc;
    }
    float* o = g_d1 + (size_t)b * 691200 + l;
    #pragma unroll 5
    for (int f = 0; f < 75; f++) {
        float d2 = s2 + 25.0f*swsq[f]
                 - 2.0f*(sw[f*3]*s1[0] + sw[f*3+1]*s1[1] + sw[f*3+2]*s1[2]);
        float d = sqrtf(fmaxf(d2, 0.0f));
        o[(size_t)f*9216] = d;
        atomicAdd(&hist[__float_as_uint(d) >> 21], 1u);
    }
    __syncthreads();
    int bb = blockIdx.x / 36;
    for (int j = t; j < 2048; j += 256)
        if (hist[j]) atomicAdd(&g_h1a[bb*2048 + j], hist[j]);
}

// ---------------- gray RBF conv (5x5) -> d1g, fused pass-1 histogram ----------------
__global__ void k_grayconv(const float* __restrict__ gray_w) {
    __shared__ float sw[625];
    __shared__ float swsq[25];
    __shared__ unsigned hist[2048];
    int t = threadIdx.x;
    for (int j = t; j < 625; j += 256) sw[j] = gray_w[j];
    for (int j = t; j < 2048; j += 256) hist[j] = 0u;
    __syncthreads();
    if (t < 25) {
        float s = 0.f;
        for (int k = 0; k < 25; k++) { float v = sw[t*25+k]; s += v*v; }
        swsq[t] = s;
    }
    __syncthreads();
    int i = blockIdx.x * 256 + t;
    int b = i / 9216, l = i - b*9216;
    int oy = l / 96, ox = l - oy*96;
    const float* gb = g_gray + (size_t)b * 10000;
    float p[25];
    float pn = 0.f;
    #pragma unroll
    for (int dy = 0; dy < 5; dy++) {
        const float* row = gb + (oy+dy)*100 + ox;
        #pragma unroll
        for (int dx = 0; dx < 5; dx++) { float v = row[dx]; p[dy*5+dx] = v; pn += v*v; }
    }
    float* o = g_d1g + (size_t)b * 230400 + l;
    #pragma unroll 5
    for (int f = 0; f < 25; f++) {
        float dot = 0.f;
        #pragma unroll
        for (int k = 0; k < 25; k++) dot += sw[f*25+k] * p[k];
        float d = sqrtf(fmaxf(pn + swsq[f] - 2.0f*dot, 0.0f));
        o[(size_t)f*9216] = d;
        atomicAdd(&hist[__float_as_uint(d) >> 21], 1u);
    }
    __syncthreads();
    int bb = blockIdx.x / 36;
    for (int j = t; j < 2048; j += 256)
        if (hist[j]) atomicAdd(&g_h1b[bb*2048 + j], hist[j]);
}

// ---------------- single-select kernels ----------------
__global__ void k_scan1p(unsigned* __restrict__ h1, int kk) {
    __shared__ unsigned scanbuf[256];
    __shared__ int ssel;
    __shared__ unsigned skrem;
    int b = blockIdx.x, tid = threadIdx.x;
    unsigned* h = h1 + b*2048;
    unsigned sel = block_kth(h, 2048, (unsigned)kk, scanbuf, &ssel, &skrem, tid);
    if (tid == 0) { g_prefix[b] = sel << 21; g_krem[b] = (int)skrem; }
    __syncthreads();
    for (int j = tid; j < 2048; j += 256) h[j] = 0u;
}

__global__ void k_hist(const float* __restrict__ data, int Nper, int shift, int nbins, int hichk) {
    __shared__ unsigned sh[2048];
    int t = threadIdx.x;
    for (int j = t; j < nbins; j += blockDim.x) sh[j] = 0u;
    __syncthreads();
    int b = blockIdx.y;
    unsigned want = g_prefix[b] >> hichk;
    const uint4* p = (const uint4*)(data + (size_t)b * Nper);
    unsigned mask = (unsigned)nbins - 1u;
    int n4 = Nper >> 2;
    for (int i = blockIdx.x * blockDim.x + t; i < n4; i += gridDim.x * blockDim.x) {
        uint4 u = p[i];
        if ((u.x >> hichk) == want) atomicAdd(&sh[(u.x >> shift) & mask], 1u);
        if ((u.y >> hichk) == want) atomicAdd(&sh[(u.y >> shift) & mask], 1u);
        if ((u.z >> hichk) == want) atomicAdd(&sh[(u.z >> shift) & mask], 1u);
        if ((u.w >> hichk) == want) atomicAdd(&sh[(u.w >> shift) & mask], 1u);
    }
    __syncthreads();
    for (int j = t; j < nbins; j += blockDim.x)
        if (sh[j]) atomicAdd(&g_histo[b*2048+j], sh[j]);
}

__global__ void k_scanp(int nbins, int shift, int finalize, const float* wptr, float* thrOut) {
    __shared__ unsigned scanbuf[256];
    __shared__ int ssel;
    __shared__ unsigned skrem;
    int b = blockIdx.x, tid = threadIdx.x;
    unsigned* h = &g_histo[b*2048];
    unsigned sel = block_kth(h, nbins, (unsigned)g_krem[b], scanbuf, &ssel, &skrem, tid);
    if (tid == 0) {
        g_prefix[b] |= sel << shift;
        g_krem[b] = (int)skrem;
        if (finalize) thrOut[b] = fminf(__uint_as_float(g_prefix[b]), wptr[0]);
    }
    __syncthreads();
    for (int j = tid; j < 2048; j += 256) h[j] = 0u;
}

// ---------------- merged stage-1 selects ----------------
__global__ void k_scan1m(int kkA, int kkB) {
    __shared__ unsigned scanbuf[256];
    __shared__ int ssel;
    __shared__ unsigned skrem;
    int b = blockIdx.x, tid = threadIdx.x;
    unsigned* h = (b < 32) ? &g_h1a[b*2048] : &g_h1b[(b-32)*2048];
    unsigned kk = (b < 32) ? (unsigned)kkA : (unsigned)kkB;
    unsigned sel = block_kth(h, 2048, kk, scanbuf, &ssel, &skrem, tid);
    if (tid == 0) { g_prefix[b] = sel << 21; g_krem[b] = (int)skrem; }
    __syncthreads();
    for (int j = tid; j < 2048; j += 256) h[j] = 0u;
}

__global__ void k_histm(const float* __restrict__ dA, const float* __restrict__ dB,
                        int shift, int nbins, int hichk) {
    __shared__ unsigned sh[2048];
    int t = threadIdx.x;
    for (int j = t; j < nbins; j += blockDim.x) sh[j] = 0u;
    __syncthreads();
    int yy = blockIdx.y;
    bool isA = yy < 32;
    int b = isA ? yy : yy - 32;
    int Nper = isA ? 691200 : 230400;
    const uint4* p = (const uint4*)((isA ? dA + (size_t)b*691200 : dB + (size_t)b*230400));
    unsigned want = g_prefix[yy] >> hichk;
    unsigned mask = (unsigned)nbins - 1u;
    int n4 = Nper >> 2;
    for (int i = blockIdx.x * blockDim.x + t; i < n4; i += gridDim.x * blockDim.x) {
        uint4 u = p[i];
        if ((u.x >> hichk) == want) atomicAdd(&sh[(u.x >> shift) & mask], 1u);
        if ((u.y >> hichk) == want) atomicAdd(&sh[(u.y >> shift) & mask], 1u);
        if ((u.z >> hichk) == want) atomicAdd(&sh[(u.z >> shift) & mask], 1u);
        if ((u.w >> hichk) == want) atomicAdd(&sh[(u.w >> shift) & mask], 1u);
    }
    __syncthreads();
    for (int j = t; j < nbins; j += blockDim.x)
        if (sh[j]) atomicAdd(&g_histo[yy*2048+j], sh[j]);
}

__global__ void k_scanm(int nbins, int shift, int finalize, const float* wptr) {
    __shared__ unsigned scanbuf[256];
    __shared__ int ssel;
    __shared__ unsigned skrem;
    int b = blockIdx.x, tid = threadIdx.x;
    unsigned* h = &g_histo[b*2048];
    unsigned sel = block_kth(h, nbins, (unsigned)g_krem[b], scanbuf, &ssel, &skrem, tid);
    if (tid == 0) {
        g_prefix[b] |= sel << shift;
        g_krem[b] = (int)skrem;
        if (finalize) {
            float thr = fminf(__uint_as_float(g_prefix[b]), wptr[0]);
            if (b < 32) g_thrA[b] = thr; else g_thrB[b-32] = thr;
        }
    }
    __syncthreads();
    for (int j = tid; j < 2048; j += 256) h[j] = 0u;
}

// ---------------- fused triangle + sfm (stage 1) ----------------
__global__ void k_sfm1(const float* __restrict__ w1) {
    int i = blockIdx.x * blockDim.x + threadIdx.x;
    if (i >= BATCH*230400) return;
    int b = i / 230400;
    int r = i - b*230400;
    int c = r / 2304;
    int l = r - c*2304;
    int oy = l / 48, ox = l - oy*48;
    float thr;
    const float* src;
    if (c < 75) { thr = g_thrA[b]; src = g_d1  + (size_t)b*691200 + (size_t)c*9216; }
    else        { thr = g_thrB[b]; src = g_d1g + (size_t)b*230400 + (size_t)(c-75)*9216; }
    float invw = 1.0f / w1[0];
    int y = 2*oy, x2 = 2*ox;
    float v00 = tri_val(src[y*96 + x2],       thr, invw);
    float v01 = tri_val(src[y*96 + x2 + 1],   thr, invw);
    float v10 = tri_val(src[(y+1)*96 + x2],   thr, invw);
    float v11 = tri_val(src[(y+1)*96 + x2+1], thr, invw);
    g_act2[i] = 0.25f * (0.90f*v00 + 0.93f*v01 + 0.96f*v10 + 0.99f*v11);
}

// ---------------- fused triangle + sfm (stage 2) ----------------
__global__ void k_sfm2(const float* __restrict__ w2) {
    int i = blockIdx.x * blockDim.x + threadIdx.x;
    if (i >= BATCH*129600) return;
    int b = i / 129600;
    int r = i - b*129600;
    int c = r / 576;
    int l = r - c*576;
    int oy = l / 24, ox = l - oy*24;
    float thr = g_thrA[b];
    float invw = 1.0f / w2[0];
    const float* src = g_d2 + ((size_t)b*225 + c) * 2304;
    int y = 2*oy, x2 = 2*ox;
    float v00 = tri_val(src[y*48 + x2],       thr, invw);
    float v01 = tri_val(src[y*48 + x2 + 1],   thr, invw);
    float v10 = tri_val(src[(y+1)*48 + x2],   thr, invw);
    float v11 = tri_val(src[(y+1)*48 + x2+1], thr, invw);
    g_act3[i] = 0.25f * (0.90f*v00 + 0.93f*v01 + 0.96f*v10 + 0.99f*v11);
}

// ---------------- staged-smem im2col -> single bf16 + row s2 (of rounded values) ----------------
__global__ void __launch_bounds__(256) k_im2col_stage(
    const float* __restrict__ in,
    __nv_bfloat16* __restrict__ outh,
    float* __restrict__ s2out,
    int C, int Hin, int Win, int oh, int ow, int pad, int Ktrue, int Kpad)
{
    extern __shared__ char smraw[];
    float* sm = (float*)smraw;
    int W2 = Win + 2*pad;
    int stageN = C * 3 * W2;
    int* kcol = (int*)(smraw + (size_t)stageN * 4);

    int bid = blockIdx.x;
    int b = bid / oh, oy = bid - b*oh;
    int tid = threadIdx.x;

    for (int k = tid; k < Ktrue; k += 256) {
        int c = k / 9; int r = k - c*9; int di = r / 3; int dj = r - di*3;
        kcol[k] = (c*3 + di)*W2 + dj;
    }
    const float* inb = in + (size_t)b * C * Hin * Win;
    for (int idx = tid; idx < stageN; idx += 256) {
        int c = idx / (3*W2); int rem = idx - c*3*W2;
        int dy = rem / W2; int xx = rem - dy*W2;
        int iy = oy + dy - pad; int ix = xx - pad;
        float v = 0.f;
        if (iy >= 0 && iy < Hin && ix >= 0 && ix < Win)
            v = inb[((size_t)c*Hin + iy)*Win + ix];
        sm[idx] = v;
    }
    __syncthreads();

    int L = oh * ow;
    int mbase = b*L + oy*ow;
    int KH = Kpad >> 1;
    int total = ow * KH;
    int ox = tid / KH, p = tid - ox*KH;
    for (int j = tid; j < total; j += 256) {
        int k0 = p*2, k1 = k0 + 1;
        float v0 = (k0 < Ktrue) ? sm[kcol[k0] + ox] : 0.f;
        float v1 = (k1 < Ktrue) ? sm[kcol[k1] + ox] : 0.f;
        __nv_bfloat16 h0 = __float2bfloat16(v0);
        __nv_bfloat16 h1 = __float2bfloat16(v1);
        size_t off = (size_t)(mbase + ox) * Kpad + k0;
        *(__nv_bfloat162*)(outh + off) = __nv_bfloat162(h0, h1);
        p += 256;
        if (p >= KH) { p -= KH; ox++; }
    }

    int wid = tid >> 5, lane = tid & 31;
    for (int oxx = wid; oxx < ow; oxx += 8) {
        float s = 0.f;
        for (int k = lane; k < Ktrue; k += 32) {
            float v = sm[kcol[k] + oxx];
            float rec = __bfloat162float(__float2bfloat16(v));
            s += rec*rec;
        }
        #pragma unroll
        for (int o2 = 16; o2 > 0; o2 >>= 1) s += __shfl_down_sync(0xFFFFFFFFu, s, o2);
        if (lane == 0) s2out[mbase + oxx] = s;
    }
}

// ---------------- weight prep: pad + bf16 split ----------------
__global__ void k_wprep(const float* __restrict__ w,
                        __nv_bfloat16* __restrict__ outh, __nv_bfloat16* __restrict__ outl,
                        int N, int K, int Npad, int Kpad) {
    int i = blockIdx.x * blockDim.x + threadIdx.x;
    if (i >= Npad*Kpad) return;
    int n = i / Kpad, k = i - n*Kpad;
    float v = (n < N && k < K) ? w[(size_t)n*K + k] : 0.f;
    __nv_bfloat16 h = __float2bfloat16(v);
    outh[i] = h;
    outl[i] = __float2bfloat16(v - __bfloat162float(h));
}

__global__ void k_rowsq_hl(const __nv_bfloat16* __restrict__ H, const __nv_bfloat16* __restrict__ Lo,
                           float* __restrict__ out, int rows, int Kp) {
    int w = (blockIdx.x * blockDim.x + threadIdx.x) >> 5;
    int lane = threadIdx.x & 31;
    if (w >= rows) return;
    const __nv_bfloat162* h2 = (const __nv_bfloat162*)(H  + (size_t)w * Kp);
    const __nv_bfloat162* l2 = (const __nv_bfloat162*)(Lo + (size_t)w * Kp);
    int K2 = Kp >> 1;
    float s = 0.f;
    for (int k = lane; k < K2; k += 32) {
        __nv_bfloat162 a = h2[k], b = l2[k];
        float v0 = __bfloat162float(a.x) + __bfloat162float(b.x);
        float v1 = __bfloat162float(a.y) + __bfloat162float(b.y);
        s += v0*v0 + v1*v1;
    }
    #pragma unroll
    for (int off = 16; off > 0; off >>= 1) s += __shfl_down_sync(0xFFFFFFFFu, s, off);
    if (lane == 0) out[w] = s;
}

// ---------------- HMMA bf16x2 GEMM with RBF epilogue + fused pass-1 histogram ----------------
// SPLITA=1: A side hi/lo (weights), W side single (im2col). 2 mma: Ah*B + Al*B.
// SPLITA=0: A side single (im2col), W side hi/lo (weights). 2 mma: A*Wh + A*Wl.
#define A_TILE  32768

__device__ __forceinline__ void prefetch_rows(uint32_t sdst, const __nv_bfloat16* __restrict__ src,
                                              int row0, int Kpad, int k0, int tid, int nrows) {
    for (int i = tid; i < nrows*8; i += 256) {
        int row = i >> 3, c8 = i & 7;
        cp16(sdst + SWZ128(row*128 + c8*16),
             src + (size_t)(row0 + row) * Kpad + k0 + c8*8);
    }
}

template<int MODE, int NFR, int SPLITA>
__global__ void __launch_bounds__(256, 1)
k_gemm_mma(const __nv_bfloat16* __restrict__ Ah, const __nv_bfloat16* __restrict__ Al,
           const __nv_bfloat16* __restrict__ Wh, const __nv_bfloat16* __restrict__ Wl,
           const float* __restrict__ s2m, const float* __restrict__ s2n,
           float* __restrict__ out, int Kpad, int NC, int Mlim, int Nlim, int L, int NW,
           unsigned* __restrict__ h1)
{
    constexpr int NT = NFR * 16;
    constexpr int W_TILE = NT * 128;
    constexpr int BUF = SPLITA ? (2*A_TILE + W_TILE) : (A_TILE + 2*W_TILE);

    extern __shared__ char dsm[];
    const int tid  = threadIdx.x;
    const int wid  = tid >> 5;
    const int lane = tid & 31;
    const int m0 = blockIdx.y * 256;
    const int n0 = blockIdx.x * NT;
    const int m_w = (wid >> 1) * 64;
    const int n_w = (wid & 1) * (NFR*8);

    uint32_t sbase = smem_u32(dsm);

    float acc[4][NFR][4];
    #pragma unroll
    for (int a = 0; a < 4; a++)
        #pragma unroll
        for (int b = 0; b < NFR; b++)
            #pragma unroll
            for (int c = 0; c < 4; c++) acc[a][b][c] = 0.f;

    const int g  = lane >> 3;
    const int rr = lane & 7;
    const int a_row  = m_w + (g & 1)*8 + rr;
    const int a_colg = (g >> 1) * 16;
    const int b_row  = n_w + (g >> 1)*8 + rr;
    const int b_colg = (g & 1) * 16;

    // prologue
    if (SPLITA) {
        prefetch_rows(sbase,                   Ah, m0, Kpad, 0, tid, 256);
        prefetch_rows(sbase + A_TILE,          Al, m0, Kpad, 0, tid, 256);
        prefetch_rows(sbase + 2*A_TILE,        Wh, n0, Kpad, 0, tid, NT);
    } else {
        prefetch_rows(sbase,                   Ah, m0, Kpad, 0, tid, 256);
        prefetch_rows(sbase + A_TILE,          Wh, n0, Kpad, 0, tid, NT);
        prefetch_rows(sbase + A_TILE + W_TILE, Wl, n0, Kpad, 0, tid, NT);
    }
    CP_COMMIT();

    for (int ch = 0; ch < NC; ch++) {
        if (ch + 1 < NC) {
            uint32_t nb = sbase + ((ch+1) & 1) * BUF;
            int k0 = (ch+1) * 64;
            if (SPLITA) {
                prefetch_rows(nb,                   Ah, m0, Kpad, k0, tid, 256);
                prefetch_rows(nb + A_TILE,          Al, m0, Kpad, k0, tid, 256);
                prefetch_rows(nb + 2*A_TILE,        Wh, n0, Kpad, k0, tid, NT);
            } else {
                prefetch_rows(nb,                   Ah, m0, Kpad, k0, tid, 256);
                prefetch_rows(nb + A_TILE,          Wh, n0, Kpad, k0, tid, NT);
                prefetch_rows(nb + A_TILE + W_TILE, Wl, n0, Kpad, k0, tid, NT);
            }
            CP_COMMIT();
            CP_WAIT1();
        } else {
            CP_WAIT0();
        }
        __syncthreads();

        uint32_t buf = sbase + (ch & 1) * BUF;

        #pragma unroll
        for (int ks = 0; ks < 4; ks++) {
            int acol = ks*32 + a_colg;
            int bcol = ks*32 + b_colg;
            if (SPLITA) {
                uint32_t tA0 = buf, tA1 = buf + A_TILE, tW0 = buf + 2*A_TILE;
                uint32_t ah[4][4], al[4][4];
                #pragma unroll
                for (int mf = 0; mf < 4; mf++) {
                    uint32_t off = SWZ128((a_row + mf*16)*128 + acol);
                    ldm_x4(ah[mf], tA0 + off);
                    ldm_x4(al[mf], tA1 + off);
                }
                #pragma unroll
                for (int q = 0; q < NFR/2; q++) {
                    uint32_t off = SWZ128((b_row + q*16)*128 + bcol);
                    uint32_t bb[4];
                    ldm_x4(bb, tW0 + off);
                    #pragma unroll
                    for (int mf = 0; mf < 4; mf++)
                        #pragma unroll
                        for (int hlf = 0; hlf < 2; hlf++) {
                            int nf = q*2 + hlf;
                            mma_bf16(acc[mf][nf], ah[mf], &bb[hlf*2]);
                            mma_bf16(acc[mf][nf], al[mf], &bb[hlf*2]);
                        }
                }
            } else {
                uint32_t tA0 = buf, tW0 = buf + A_TILE, tW1 = buf + A_TILE + W_TILE;
                uint32_t aa[4][4];
                #pragma unroll
                for (int mf = 0; mf < 4; mf++) {
                    uint32_t off = SWZ128((a_row + mf*16)*128 + acol);
                    ldm_x4(aa[mf], tA0 + off);
                }
                #pragma unroll
                for (int q = 0; q < NFR/2; q++) {
                    uint32_t off = SWZ128((b_row + q*16)*128 + bcol);
                    uint32_t bh[4], bl[4];
                    ldm_x4(bh, tW0 + off);
                    ldm_x4(bl, tW1 + off);
                    #pragma unroll
                    for (int mf = 0; mf < 4; mf++)
                        #pragma unroll
                        for (int hlf = 0; hlf < 2; hlf++) {
                            int nf = q*2 + hlf;
                            mma_bf16(acc[mf][nf], aa[mf], &bh[hlf*2]);
                            mma_bf16(acc[mf][nf], aa[mf], &bl[hlf*2]);
                        }
                }
            }
        }
        __syncthreads();
    }

    unsigned* sh = (unsigned*)dsm;
    for (int i = tid; i < 4096; i += 256) sh[i] = 0u;
    __syncthreads();

    const int b_base = (MODE ? n0 : m0) / L;
    const int tg = lane >> 2, tk = lane & 3;
    #pragma unroll
    for (int mf = 0; mf < 4; mf++) {
        #pragma unroll
        for (int h = 0; h < 2; h++) {
            int m = m0 + m_w + mf*16 + tg + h*8;
            if (m >= Mlim) continue;
            float smv = s2m[m];
            if (MODE == 0) {
                int b = m / L;
                int l = m - b*L;
                float* ob = out + ((size_t)b*NW)*L + l;
                int slot = (b - b_base) << 11;
                #pragma unroll
                for (int nf = 0; nf < NFR; nf++) {
                    #pragma unroll
                    for (int j = 0; j < 2; j++) {
                        int n = n0 + n_w + nf*8 + tk*2 + j;
                        if (n >= Nlim) continue;
                        float d2v = smv + s2n[n] - 2.0f * acc[mf][nf][h*2 + j];
                        float d = sqrtf(fmaxf(d2v, 0.0f));
                        ob[(size_t)n * L] = d;
                        atomicAdd(&sh[slot | (__float_as_uint(d) >> 21)], 1u);
                    }
                }
            } else {
                #pragma unroll
                for (int nf = 0; nf < NFR; nf++) {
                    #pragma unroll
                    for (int j = 0; j < 2; j++) {
                        int n = n0 + n_w + nf*8 + tk*2 + j;
                        if (n >= Nlim) continue;
                        int b = n / L;
                        int l = n - b*L;
                        float d2v = smv + s2n[n] - 2.0f * acc[mf][nf][h*2 + j];
                        float d = sqrtf(fmaxf(d2v, 0.0f));
                        out[((size_t)b*NW + m)*L + l] = d;
                        atomicAdd(&sh[((b - b_base) << 11) | (__float_as_uint(d) >> 21)], 1u);
                    }
                }
            }
        }
    }
    __syncthreads();
    for (int i = tid; i < 4096; i += 256) {
        unsigned v = sh[i];
        int bb = b_base + (i >> 11);
        if (v && bb < BATCH) atomicAdd(&h1[bb*2048 + (i & 2047)], v);
    }
}

// ---------------- fused triangle + FC: chunked partials ----------------
#define FC_CHUNK_LEN 4727
__global__ void __launch_bounds__(256) k_fcpart(const float* __restrict__ fcw,
                                                const float* __restrict__ w3) {
    int chunk = blockIdx.x, b = blockIdx.y;
    int k0 = chunk * FC_CHUNK_LEN;
    int k1 = k0 + FC_CHUNK_LEN; if (k1 > 75625) k1 = 75625;
    float thr = g_thrA[b];
    float invw = 1.0f / w3[0];
    const float4* src = (const float4*)(g_d3 + (size_t)b * 302500);
    float acc[10];
    #pragma unroll
    for (int n = 0; n < 10; n++) acc[n] = 0.f;
    for (int k = k0 + threadIdx.x; k < k1; k += 256) {
        float4 v = src[k];
        float t0 = (v.x > thr ? 0.f : 1.f - v.x*invw);
        float t1 = (v.y > thr ? 0.f : 1.f - v.y*invw);
        float t2 = (v.z > thr ? 0.f : 1.f - v.z*invw);
        float t3 = (v.w > thr ? 0.f : 1.f - v.w*invw);
        #pragma unroll
        for (int n = 0; n < 10; n++) {
            float4 w = ((const float4*)(fcw + (size_t)n * 302500))[k];
            acc[n] += t0*w.x + t1*w.y + t2*w.z + t3*w.w;
        }
    }
    __shared__ float red[256];
    #pragma unroll
    for (int n = 0; n < 10; n++) {
        red[threadIdx.x] = acc[n];
        __syncthreads();
        for (int st = 128; st > 0; st >>= 1) {
            if (threadIdx.x < st) red[threadIdx.x] += red[threadIdx.x + st];
            __syncthreads();
        }
        if (threadIdx.x == 0) g_fcpart[((size_t)chunk*BATCH + b)*10 + n] = red[0];
        __syncthreads();
    }
}

__global__ void k_fcfin(const float* __restrict__ fcb, float* __restrict__ out) {
    int i = threadIdx.x;
    if (i >= BATCH*10) return;
    int n = i % 10;
    float s = fcb[n];
    for (int c = 0; c < FC_CHUNKS; c++) s += g_fcpart[(size_t)c*BATCH*10 + i];
    out[i] = s;
}

// ---------------- host side ----------------
static void run_select(unsigned* h1, const float* data, int Nper, int kk,
                       const float* wptr, float* thrOut) {
    k_scan1p<<<BATCH, 256>>>(h1, kk);
    k_hist<<<dim3(64, BATCH), 256>>>(data, Nper, 10, 2048, 21);
    k_scanp<<<BATCH, 256>>>(2048, 10, 0, nullptr, nullptr);
    k_hist<<<dim3(64, BATCH), 256>>>(data, Nper, 0, 1024, 10);
    k_scanp<<<BATCH, 256>>>(1024, 0, 1, wptr, thrOut);
}

extern "C" void kernel_launch(void* const* d_in, const int* in_sizes, int n_in,
                              void* d_out, int out_size) {
    const float* x       = (const float*)d_in[0];
    const float* rgb_w   = (const float*)d_in[1];
    const float* gray_w  = (const float*)d_in[2];
    const float* conv1_w = (const float*)d_in[3];
    const float* conv2_w = (const float*)d_in[4];
    const float* fc_w    = (const float*)d_in[5];
    const float* fc_b    = (const float*)d_in[6];
    const float* w1      = (const float*)d_in[7];
    const float* w2      = (const float*)d_in[8];
    const float* w3      = (const float*)d_in[9];
    float* out = (float*)d_out;

    void *pd1, *pd1g, *pact2, *pact3, *pd2, *pd3, *pthrA, *pthrB;
    void *pc1h, *pc2h, *pw1h, *pw1l, *pw2h, *pw2l;
    void *ps2a, *ps2b, *pwsq1, *pwsq2, *ph1a, *ph1b;
    cudaGetSymbolAddress(&pd1,   g_d1);
    cudaGetSymbolAddress(&pd1g,  g_d1g);
    cudaGetSymbolAddress(&pact2, g_act2);
    cudaGetSymbolAddress(&pact3, g_act3);
    cudaGetSymbolAddress(&pd2,   g_d2);
    cudaGetSymbolAddress(&pd3,   g_d3);
    cudaGetSymbolAddress(&pthrA, g_thrA);
    cudaGetSymbolAddress(&pthrB, g_thrB);
    cudaGetSymbolAddress(&pc1h,  g_col1h);
    cudaGetSymbolAddress(&pc2h,  g_col2h);
    cudaGetSymbolAddress(&pw1h,  g_w1h);
    cudaGetSymbolAddress(&pw1l,  g_w1l);
    cudaGetSymbolAddress(&pw2h,  g_w2h);
    cudaGetSymbolAddress(&pw2l,  g_w2l);
    cudaGetSymbolAddress(&ps2a,  g_s2a);
    cudaGetSymbolAddress(&ps2b,  g_s2b);
    cudaGetSymbolAddress(&pwsq1, g_wsq1);
    cudaGetSymbolAddress(&pwsq2, g_wsq2);
    cudaGetSymbolAddress(&ph1a,  g_h1a);
    cudaGetSymbolAddress(&ph1b,  g_h1b);

    // conv1: SPLITA=1 (weights hi/lo on A side, im2col single on W side): BUF=2*32K+16K=80K, x2=160K
    cudaFuncSetAttribute((const void*)k_gemm_mma<1,8,1>,  cudaFuncAttributeMaxDynamicSharedMemorySize, 163840);
    // conv2: SPLITA=0 (im2col single on A side, weights hi/lo on W side): BUF=32K+2*20K=72K, x2=144K
    cudaFuncSetAttribute((const void*)k_gemm_mma<0,10,0>, cudaFuncAttributeMaxDynamicSharedMemorySize, 147456);
    cudaFuncSetAttribute(k_im2col_stage, cudaFuncAttributeMaxDynamicSharedMemorySize, 81008);

    // stage 1
    k_gray<<<(BATCH*10000 + 255)/256, 256>>>(x);
    k_rgbconv<<<1152, 256>>>(x, rgb_w);
    k_grayconv<<<1152, 256>>>(gray_w);
    k_scan1m<<<64, 256>>>(345600, 115200);
    k_histm<<<dim3(64, 64), 256>>>((const float*)pd1, (const float*)pd1g, 10, 2048, 21);
    k_scanm<<<64, 256>>>(2048, 10, 0, w1);
    k_histm<<<dim3(64, 64), 256>>>((const float*)pd1, (const float*)pd1g, 0, 1024, 10);
    k_scanm<<<64, 256>>>(1024, 0, 1, w1);
    k_sfm1<<<(BATCH*230400 + 255)/256, 256>>>(w1);

    // conv1 (RBF, k=3, pad=1): (B,100,48,48) -> (B,225,48,48)
    k_im2col_stage<<<1536, 256, 63600>>>((const float*)pact2,
        (__nv_bfloat16*)pc1h, (float*)ps2a, 100, 48, 48, 48, 48, 1, 900, 960);
    k_wprep<<<(256*960 + 255)/256, 256>>>(conv1_w, (__nv_bfloat16*)pw1h, (__nv_bfloat16*)pw1l,
                                          225, 900, 256, 960);
    k_rowsq_hl<<<(256*32 + 255)/256, 256>>>((const __nv_bfloat16*)pw1h, (const __nv_bfloat16*)pw1l,
                                            (float*)pwsq1, 256, 960);
    k_gemm_mma<1,8,1><<<dim3(576, 1), 256, 163840>>>(
        (const __nv_bfloat16*)pw1h, (const __nv_bfloat16*)pw1l,
        (const __nv_bfloat16*)pc1h, nullptr,
        (const float*)pwsq1, (const float*)ps2a, (float*)pd2,
        960, 15, 225, 73728, 2304, 225, (unsigned*)ph1a);
    run_select((unsigned*)ph1a, (const float*)pd2, 518400, 207360, w2, (float*)pthrA);
    k_sfm2<<<(BATCH*129600 + 255)/256, 256>>>(w2);

    // conv2 (RBF, k=3, pad=0): (B,225,24,24) -> (B,625,22,22), N-tile 160 (244 CTAs = 2 waves)
    k_im2col_stage<<<704, 256, 81008>>>((const float*)pact3,
        (__nv_bfloat16*)pc2h, (float*)ps2b, 225, 24, 24, 22, 22, 0, 2025, 2048);
    k_wprep<<<(640*2048 + 255)/256, 256>>>(conv2_w, (__nv_bfloat16*)pw2h, (__nv_bfloat16*)pw2l,
                                           625, 2025, 640, 2048);
    k_rowsq_hl<<<(640*32 + 255)/256, 256>>>((const __nv_bfloat16*)pw2h, (const __nv_bfloat16*)pw2l,
                                            (float*)pwsq2, 640, 2048);
    k_gemm_mma<0,10,0><<<dim3(4, 61), 256, 147456>>>(
        (const __nv_bfloat16*)pc2h, nullptr,
        (const __nv_bfloat16*)pw2h, (const __nv_bfloat16*)pw2l,
        (const float*)ps2b, (const float*)pwsq2, (float*)pd3,
        2048, 32, 15488, 625, 484, 625, (unsigned*)ph1a);
    run_select((unsigned*)ph1a, (const float*)pd3, 302500, 121000, w3, (float*)pthrA);

    // fused triangle + FC
    k_fcpart<<<dim3(FC_CHUNKS, BATCH), 256>>>(fc_w, w3);
    k_fcfin<<<1, 320>>>(fc_b, out);
}

// round 15
// speedup vs baseline: 1.7031x; 1.1890x over previous
#include <cuda_runtime.h>
#include <cuda_bf16.h>
#include <math.h>
#include <stdint.h>

#define BATCH 32

// ---------------- persistent scratch (device globals; no allocation) ----------------
__device__ float g_gray[BATCH*10000];
__device__ float g_d1 [BATCH*691200];
__device__ float g_d1g[BATCH*230400];
__device__ float g_act2[BATCH*230400];
__device__ float g_act3[BATCH*129600];
__device__ float g_d2 [BATCH*518400];
__device__ float g_d3 [BATCH*302500];

// operands: BOTH sides stored as single rounded bf16
__device__ __align__(16) __nv_bfloat16 g_col1h[73728*960];
__device__ __align__(16) __nv_bfloat16 g_col2h[15616*2048];
__device__ __align__(16) __nv_bfloat16 g_w1h[256*960];
__device__ __align__(16) __nv_bfloat16 g_w2h[640*2048];
__device__ float g_s2a [73728];
__device__ float g_s2b [15616];
__device__ float g_wsq1[256];
__device__ float g_wsq2[640];

__device__ unsigned g_histo[64*2048];
__device__ unsigned g_h1a[BATCH*2048];
__device__ unsigned g_h1b[BATCH*2048];
__device__ unsigned g_prefix[64];
__device__ int      g_krem[64];
__device__ float    g_thrA[BATCH];
__device__ float    g_thrB[BATCH];

#define FC_CHUNKS 16
__device__ float g_fcpart[FC_CHUNKS*BATCH*10];

// ---------------- ptx helpers ----------------
__device__ __forceinline__ uint32_t smem_u32(const void* p) {
    uint32_t a;
    asm("{ .reg .u64 t; cvta.to.shared.u64 t, %1; cvt.u32.u64 %0, t; }" : "=r"(a) : "l"(p));
    return a;
}
__device__ __forceinline__ void cp16(uint32_t dst, const void* src) {
    asm volatile("cp.async.cg.shared.global [%0], [%1], 16;" :: "r"(dst), "l"(src));
}
#define CP_COMMIT() asm volatile("cp.async.commit_group;" ::: "memory")
#define CP_WAIT1()  asm volatile("cp.async.wait_group 1;" ::: "memory")
#define CP_WAIT0()  asm volatile("cp.async.wait_group 0;" ::: "memory")

__device__ __forceinline__ void ldm_x4(uint32_t* r, uint32_t addr) {
    asm volatile("ldmatrix.sync.aligned.m8n8.x4.shared.b16 {%0,%1,%2,%3}, [%4];"
                 : "=r"(r[0]), "=r"(r[1]), "=r"(r[2]), "=r"(r[3]) : "r"(addr));
}
__device__ __forceinline__ void mma_bf16(float* d, const uint32_t* a, const uint32_t* b) {
    asm volatile("mma.sync.aligned.m16n8k16.row.col.f32.bf16.bf16.f32 "
                 "{%0,%1,%2,%3}, {%4,%5,%6,%7}, {%8,%9}, {%0,%1,%2,%3};"
                 : "+f"(d[0]), "+f"(d[1]), "+f"(d[2]), "+f"(d[3])
                 : "r"(a[0]), "r"(a[1]), "r"(a[2]), "r"(a[3]), "r"(b[0]), "r"(b[1]));
}
#define SWZ128(x) ((x) ^ (((x) >> 3) & 0x70))

__device__ __forceinline__ float tri_val(float v, float thr, float invw) {
    return (v > thr) ? 0.0f : 1.0f - v * invw;
}

// ---------------- parallel k-th-bin search ----------------
__device__ __forceinline__ unsigned block_kth(const unsigned* hist, int nbins, unsigned k,
                                              unsigned* scanbuf, int* sel_sm, unsigned* krem_sm,
                                              int tid) {
    int per = nbins >> 8;
    int base = tid * per;
    unsigned own = 0;
    for (int j = 0; j < per; j++) own += hist[base + j];
    scanbuf[tid] = own;
    __syncthreads();
    for (int off = 1; off < 256; off <<= 1) {
        unsigned v = (tid >= off) ? scanbuf[tid - off] : 0u;
        __syncthreads();
        scanbuf[tid] += v;
        __syncthreads();
    }
    unsigned incl = scanbuf[tid];
    unsigned excl = incl - own;
    if (excl < k && incl >= k) {
        unsigned c = excl;
        for (int j = 0; j < per; j++) {
            unsigned v = hist[base + j];
            if (c + v >= k) { *sel_sm = base + j; *krem_sm = k - c; break; }
            c += v;
        }
    }
    __syncthreads();
    return (unsigned)*sel_sm;
}

// ---------------- grayscale ----------------
__global__ void k_gray(const float* __restrict__ x) {
    int i = blockIdx.x * blockDim.x + threadIdx.x;
    if (i >= BATCH*10000) return;
    int b = i / 10000, p = i - b*10000;
    const float* xb = x + (size_t)b * 30000;
    g_gray[i] = 0.2989f*xb[p] + 0.587f*xb[10000+p] + 0.114f*xb[20000+p];
}

// ---------------- rgb conv (5x5) -> d1, fused pass-1 histogram ----------------
__global__ void k_rgbconv(const float* __restrict__ x, const float* __restrict__ rgb_w) {
    __shared__ float sw[225];
    __shared__ float swsq[75];
    __shared__ unsigned hist[2048];
    int t = threadIdx.x;
    if (t < 225) sw[t] = rgb_w[t];
    for (int j = t; j < 2048; j += 256) hist[j] = 0u;
    __syncthreads();
    if (t < 75) {
        float a = sw[t*3], b2 = sw[t*3+1], c = sw[t*3+2];
        swsq[t] = a*a + b2*b2 + c*c;
    }
    __syncthreads();
    int i = blockIdx.x * 256 + t;
    int b = i / 9216, l = i - b*9216;
    int oy = l / 96, ox = l - oy*96;
    const float* xb = x + (size_t)b * 30000;
    float s1[3];
    float s2 = 0.f;
    #pragma unroll
    for (int c = 0; c < 3; c++) {
        float sc = 0.f;
        const float* xc = xb + c*10000;
        #pragma unroll
        for (int dy = 0; dy < 5; dy++) {
            const float* row = xc + (oy+dy)*100 + ox;
            #pragma unroll
            for (int dx = 0; dx < 5; dx++) { float v = row[dx]; sc += v; s2 += v*v; }
        }
        s1[c] = sc;
    }
    float* o = g_d1 + (size_t)b * 691200 + l;
    #pragma unroll 5
    for (int f = 0; f < 75; f++) {
        float d2 = s2 + 25.0f*swsq[f]
                 - 2.0f*(sw[f*3]*s1[0] + sw[f*3+1]*s1[1] + sw[f*3+2]*s1[2]);
        float d = sqrtf(fmaxf(d2, 0.0f));
        o[(size_t)f*9216] = d;
        atomicAdd(&hist[__float_as_uint(d) >> 21], 1u);
    }
    __syncthreads();
    int bb = blockIdx.x / 36;
    for (int j = t; j < 2048; j += 256)
        if (hist[j]) atomicAdd(&g_h1a[bb*2048 + j], hist[j]);
}

// ---------------- gray RBF conv (5x5) -> d1g, fused pass-1 histogram ----------------
__global__ void k_grayconv(const float* __restrict__ gray_w) {
    __shared__ float sw[625];
    __shared__ float swsq[25];
    __shared__ unsigned hist[2048];
    int t = threadIdx.x;
    for (int j = t; j < 625; j += 256) sw[j] = gray_w[j];
    for (int j = t; j < 2048; j += 256) hist[j] = 0u;
    __syncthreads();
    if (t < 25) {
        float s = 0.f;
        for (int k = 0; k < 25; k++) { float v = sw[t*25+k]; s += v*v; }
        swsq[t] = s;
    }
    __syncthreads();
    int i = blockIdx.x * 256 + t;
    int b = i / 9216, l = i - b*9216;
    int oy = l / 96, ox = l - oy*96;
    const float* gb = g_gray + (size_t)b * 10000;
    float p[25];
    float pn = 0.f;
    #pragma unroll
    for (int dy = 0; dy < 5; dy++) {
        const float* row = gb + (oy+dy)*100 + ox;
        #pragma unroll
        for (int dx = 0; dx < 5; dx++) { float v = row[dx]; p[dy*5+dx] = v; pn += v*v; }
    }
    float* o = g_d1g + (size_t)b * 230400 + l;
    #pragma unroll 5
    for (int f = 0; f < 25; f++) {
        float dot = 0.f;
        #pragma unroll
        for (int k = 0; k < 25; k++) dot += sw[f*25+k] * p[k];
        float d = sqrtf(fmaxf(pn + swsq[f] - 2.0f*dot, 0.0f));
        o[(size_t)f*9216] = d;
        atomicAdd(&hist[__float_as_uint(d) >> 21], 1u);
    }
    __syncthreads();
    int bb = blockIdx.x / 36;
    for (int j = t; j < 2048; j += 256)
        if (hist[j]) atomicAdd(&g_h1b[bb*2048 + j], hist[j]);
}

// ---------------- single-select kernels ----------------
__global__ void k_scan1p(unsigned* __restrict__ h1, int kk) {
    __shared__ unsigned scanbuf[256];
    __shared__ int ssel;
    __shared__ unsigned skrem;
    int b = blockIdx.x, tid = threadIdx.x;
    unsigned* h = h1 + b*2048;
    unsigned sel = block_kth(h, 2048, (unsigned)kk, scanbuf, &ssel, &skrem, tid);
    if (tid == 0) { g_prefix[b] = sel << 21; g_krem[b] = (int)skrem; }
    __syncthreads();
    for (int j = tid; j < 2048; j += 256) h[j] = 0u;
}

__global__ void k_hist(const float* __restrict__ data, int Nper, int shift, int nbins, int hichk) {
    __shared__ unsigned sh[2048];
    int t = threadIdx.x;
    for (int j = t; j < nbins; j += blockDim.x) sh[j] = 0u;
    __syncthreads();
    int b = blockIdx.y;
    unsigned want = g_prefix[b] >> hichk;
    const uint4* p = (const uint4*)(data + (size_t)b * Nper);
    unsigned mask = (unsigned)nbins - 1u;
    int n4 = Nper >> 2;
    for (int i = blockIdx.x * blockDim.x + t; i < n4; i += gridDim.x * blockDim.x) {
        uint4 u = p[i];
        if ((u.x >> hichk) == want) atomicAdd(&sh[(u.x >> shift) & mask], 1u);
        if ((u.y >> hichk) == want) atomicAdd(&sh[(u.y >> shift) & mask], 1u);
        if ((u.z >> hichk) == want) atomicAdd(&sh[(u.z >> shift) & mask], 1u);
        if ((u.w >> hichk) == want) atomicAdd(&sh[(u.w >> shift) & mask], 1u);
    }
    __syncthreads();
    for (int j = t; j < nbins; j += blockDim.x)
        if (sh[j]) atomicAdd(&g_histo[b*2048+j], sh[j]);
}

__global__ void k_scanp(int nbins, int shift, int finalize, const float* wptr, float* thrOut) {
    __shared__ unsigned scanbuf[256];
    __shared__ int ssel;
    __shared__ unsigned skrem;
    int b = blockIdx.x, tid = threadIdx.x;
    unsigned* h = &g_histo[b*2048];
    unsigned sel = block_kth(h, nbins, (unsigned)g_krem[b], scanbuf, &ssel, &skrem, tid);
    if (tid == 0) {
        g_prefix[b] |= sel << shift;
        g_krem[b] = (int)skrem;
        if (finalize) thrOut[b] = fminf(__uint_as_float(g_prefix[b]), wptr[0]);
    }
    __syncthreads();
    for (int j = tid; j < 2048; j += 256) h[j] = 0u;
}

// ---------------- merged stage-1 selects ----------------
__global__ void k_scan1m(int kkA, int kkB) {
    __shared__ unsigned scanbuf[256];
    __shared__ int ssel;
    __shared__ unsigned skrem;
    int b = blockIdx.x, tid = threadIdx.x;
    unsigned* h = (b < 32) ? &g_h1a[b*2048] : &g_h1b[(b-32)*2048];
    unsigned kk = (b < 32) ? (unsigned)kkA : (unsigned)kkB;
    unsigned sel = block_kth(h, 2048, kk, scanbuf, &ssel, &skrem, tid);
    if (tid == 0) { g_prefix[b] = sel << 21; g_krem[b] = (int)skrem; }
    __syncthreads();
    for (int j = tid; j < 2048; j += 256) h[j] = 0u;
}

__global__ void k_histm(const float* __restrict__ dA, const float* __restrict__ dB,
                        int shift, int nbins, int hichk) {
    __shared__ unsigned sh[2048];
    int t = threadIdx.x;
    for (int j = t; j < nbins; j += blockDim.x) sh[j] = 0u;
    __syncthreads();
    int yy = blockIdx.y;
    bool isA = yy < 32;
    int b = isA ? yy : yy - 32;
    int Nper = isA ? 691200 : 230400;
    const uint4* p = (const uint4*)((isA ? dA + (size_t)b*691200 : dB + (size_t)b*230400));
    unsigned want = g_prefix[yy] >> hichk;
    unsigned mask = (unsigned)nbins - 1u;
    int n4 = Nper >> 2;
    for (int i = blockIdx.x * blockDim.x + t; i < n4; i += gridDim.x * blockDim.x) {
        uint4 u = p[i];
        if ((u.x >> hichk) == want) atomicAdd(&sh[(u.x >> shift) & mask], 1u);
        if ((u.y >> hichk) == want) atomicAdd(&sh[(u.y >> shift) & mask], 1u);
        if ((u.z >> hichk) == want) atomicAdd(&sh[(u.z >> shift) & mask], 1u);
        if ((u.w >> hichk) == want) atomicAdd(&sh[(u.w >> shift) & mask], 1u);
    }
    __syncthreads();
    for (int j = t; j < nbins; j += blockDim.x)
        if (sh[j]) atomicAdd(&g_histo[yy*2048+j], sh[j]);
}

__global__ void k_scanm(int nbins, int shift, int finalize, const float* wptr) {
    __shared__ unsigned scanbuf[256];
    __shared__ int ssel;
    __shared__ unsigned skrem;
    int b = blockIdx.x, tid = threadIdx.x;
    unsigned* h = &g_histo[b*2048];
    unsigned sel = block_kth(h, nbins, (unsigned)g_krem[b], scanbuf, &ssel, &skrem, tid);
    if (tid == 0) {
        g_prefix[b] |= sel << shift;
        g_krem[b] = (int)skrem;
        if (finalize) {
            float thr = fminf(__uint_as_float(g_prefix[b]), wptr[0]);
            if (b < 32) g_thrA[b] = thr; else g_thrB[b-32] = thr;
        }
    }
    __syncthreads();
    for (int j = tid; j < 2048; j += 256) h[j] = 0u;
}

// ---------------- fused triangle + sfm (stage 1) ----------------
__global__ void k_sfm1(const float* __restrict__ w1) {
    int i = blockIdx.x * blockDim.x + threadIdx.x;
    if (i >= BATCH*230400) return;
    int b = i / 230400;
    int r = i - b*230400;
    int c = r / 2304;
    int l = r - c*2304;
    int oy = l / 48, ox = l - oy*48;
    float thr;
    const float* src;
    if (c < 75) { thr = g_thrA[b]; src = g_d1  + (size_t)b*691200 + (size_t)c*9216; }
    else        { thr = g_thrB[b]; src = g_d1g + (size_t)b*230400 + (size_t)(c-75)*9216; }
    float invw = 1.0f / w1[0];
    int y = 2*oy, x2 = 2*ox;
    float v00 = tri_val(src[y*96 + x2],       thr, invw);
    float v01 = tri_val(src[y*96 + x2 + 1],   thr, invw);
    float v10 = tri_val(src[(y+1)*96 + x2],   thr, invw);
    float v11 = tri_val(src[(y+1)*96 + x2+1], thr, invw);
    g_act2[i] = 0.25f * (0.90f*v00 + 0.93f*v01 + 0.96f*v10 + 0.99f*v11);
}

// ---------------- fused triangle + sfm (stage 2) ----------------
__global__ void k_sfm2(const float* __restrict__ w2) {
    int i = blockIdx.x * blockDim.x + threadIdx.x;
    if (i >= BATCH*129600) return;
    int b = i / 129600;
    int r = i - b*129600;
    int c = r / 576;
    int l = r - c*576;
    int oy = l / 24, ox = l - oy*24;
    float thr = g_thrA[b];
    float invw = 1.0f / w2[0];
    const float* src = g_d2 + ((size_t)b*225 + c) * 2304;
    int y = 2*oy, x2 = 2*ox;
    float v00 = tri_val(src[y*48 + x2],       thr, invw);
    float v01 = tri_val(src[y*48 + x2 + 1],   thr, invw);
    float v10 = tri_val(src[(y+1)*48 + x2],   thr, invw);
    float v11 = tri_val(src[(y+1)*48 + x2+1], thr, invw);
    g_act3[i] = 0.25f * (0.90f*v00 + 0.93f*v01 + 0.96f*v10 + 0.99f*v11);
}

// ---------------- staged-smem im2col -> single bf16 + row s2 (of rounded values) ----------------
__global__ void __launch_bounds__(256) k_im2col_stage(
    const float* __restrict__ in,
    __nv_bfloat16* __restrict__ outh,
    float* __restrict__ s2out,
    int C, int Hin, int Win, int oh, int ow, int pad, int Ktrue, int Kpad)
{
    extern __shared__ char smraw[];
    float* sm = (float*)smraw;
    int W2 = Win + 2*pad;
    int stageN = C * 3 * W2;
    int* kcol = (int*)(smraw + (size_t)stageN * 4);

    int bid = blockIdx.x;
    int b = bid / oh, oy = bid - b*oh;
    int tid = threadIdx.x;

    for (int k = tid; k < Ktrue; k += 256) {
        int c = k / 9; int r = k - c*9; int di = r / 3; int dj = r - di*3;
        kcol[k] = (c*3 + di)*W2 + dj;
    }
    const float* inb = in + (size_t)b * C * Hin * Win;
    for (int idx = tid; idx < stageN; idx += 256) {
        int c = idx / (3*W2); int rem = idx - c*3*W2;
        int dy = rem / W2; int xx = rem - dy*W2;
        int iy = oy + dy - pad; int ix = xx - pad;
        float v = 0.f;
        if (iy >= 0 && iy < Hin && ix >= 0 && ix < Win)
            v = inb[((size_t)c*Hin + iy)*Win + ix];
        sm[idx] = v;
    }
    __syncthreads();

    int L = oh * ow;
    int mbase = b*L + oy*ow;
    int KH = Kpad >> 1;
    int total = ow * KH;
    int ox = tid / KH, p = tid - ox*KH;
    for (int j = tid; j < total; j += 256) {
        int k0 = p*2, k1 = k0 + 1;
        float v0 = (k0 < Ktrue) ? sm[kcol[k0] + ox] : 0.f;
        float v1 = (k1 < Ktrue) ? sm[kcol[k1] + ox] : 0.f;
        __nv_bfloat16 h0 = __float2bfloat16(v0);
        __nv_bfloat16 h1 = __float2bfloat16(v1);
        size_t off = (size_t)(mbase + ox) * Kpad + k0;
        *(__nv_bfloat162*)(outh + off) = __nv_bfloat162(h0, h1);
        p += 256;
        if (p >= KH) { p -= KH; ox++; }
    }

    int wid = tid >> 5, lane = tid & 31;
    for (int oxx = wid; oxx < ow; oxx += 8) {
        float s = 0.f;
        for (int k = lane; k < Ktrue; k += 32) {
            float v = sm[kcol[k] + oxx];
            float rec = __bfloat162float(__float2bfloat16(v));
            s += rec*rec;
        }
        #pragma unroll
        for (int o2 = 16; o2 > 0; o2 >>= 1) s += __shfl_down_sync(0xFFFFFFFFu, s, o2);
        if (lane == 0) s2out[mbase + oxx] = s;
    }
}

// ---------------- weight prep: pad + single bf16 round ----------------
__global__ void k_wprep(const float* __restrict__ w,
                        __nv_bfloat16* __restrict__ outh,
                        int N, int K, int Npad, int Kpad) {
    int i = blockIdx.x * blockDim.x + threadIdx.x;
    if (i >= Npad*Kpad) return;
    int n = i / Kpad, k = i - n*Kpad;
    float v = (n < N && k < K) ? w[(size_t)n*K + k] : 0.f;
    outh[i] = __float2bfloat16(v);
}

// per-row sum of squares of rounded weights
__global__ void k_rowsq_h(const __nv_bfloat16* __restrict__ H,
                          float* __restrict__ out, int rows, int Kp) {
    int w = (blockIdx.x * blockDim.x + threadIdx.x) >> 5;
    int lane = threadIdx.x & 31;
    if (w >= rows) return;
    const __nv_bfloat162* h2 = (const __nv_bfloat162*)(H + (size_t)w * Kp);
    int K2 = Kp >> 1;
    float s = 0.f;
    for (int k = lane; k < K2; k += 32) {
        __nv_bfloat162 a = h2[k];
        float v0 = __bfloat162float(a.x);
        float v1 = __bfloat162float(a.y);
        s += v0*v0 + v1*v1;
    }
    #pragma unroll
    for (int off = 16; off > 0; off >>= 1) s += __shfl_down_sync(0xFFFFFFFFu, s, off);
    if (lane == 0) out[w] = s;
}

// ---------------- HMMA bf16x1 GEMM with RBF epilogue + fused pass-1 histogram ----------------
// Both operands single bf16: 1 mma per fragment pair. d = ||Ar - Wr|| exact in fp32 accum.
#define A_TILE  32768

__device__ __forceinline__ void prefetch_rows(uint32_t sdst, const __nv_bfloat16* __restrict__ src,
                                              int row0, int Kpad, int k0, int tid, int nrows) {
    for (int i = tid; i < nrows*8; i += 256) {
        int row = i >> 3, c8 = i & 7;
        cp16(sdst + SWZ128(row*128 + c8*16),
             src + (size_t)(row0 + row) * Kpad + k0 + c8*8);
    }
}

template<int MODE, int NFR>
__global__ void __launch_bounds__(256, 1)
k_gemm_mma(const __nv_bfloat16* __restrict__ Ah,
           const __nv_bfloat16* __restrict__ Wh,
           const float* __restrict__ s2m, const float* __restrict__ s2n,
           float* __restrict__ out, int Kpad, int NC, int Mlim, int Nlim, int L, int NW,
           unsigned* __restrict__ h1)
{
    constexpr int NT = NFR * 16;
    constexpr int W_TILE = NT * 128;
    constexpr int BUF = A_TILE + W_TILE;

    extern __shared__ char dsm[];
    const int tid  = threadIdx.x;
    const int wid  = tid >> 5;
    const int lane = tid & 31;
    const int m0 = blockIdx.y * 256;
    const int n0 = blockIdx.x * NT;
    const int m_w = (wid >> 1) * 64;
    const int n_w = (wid & 1) * (NFR*8);

    uint32_t sbase = smem_u32(dsm);

    float acc[4][NFR][4];
    #pragma unroll
    for (int a = 0; a < 4; a++)
        #pragma unroll
        for (int b = 0; b < NFR; b++)
            #pragma unroll
            for (int c = 0; c < 4; c++) acc[a][b][c] = 0.f;

    const int g  = lane >> 3;
    const int rr = lane & 7;
    const int a_row  = m_w + (g & 1)*8 + rr;
    const int a_colg = (g >> 1) * 16;
    const int b_row  = n_w + (g >> 1)*8 + rr;
    const int b_colg = (g & 1) * 16;

    prefetch_rows(sbase,          Ah, m0, Kpad, 0, tid, 256);
    prefetch_rows(sbase + A_TILE, Wh, n0, Kpad, 0, tid, NT);
    CP_COMMIT();

    for (int ch = 0; ch < NC; ch++) {
        if (ch + 1 < NC) {
            uint32_t nb = sbase + ((ch+1) & 1) * BUF;
            int k0 = (ch+1) * 64;
            prefetch_rows(nb,          Ah, m0, Kpad, k0, tid, 256);
            prefetch_rows(nb + A_TILE, Wh, n0, Kpad, k0, tid, NT);
            CP_COMMIT();
            CP_WAIT1();
        } else {
            CP_WAIT0();
        }
        __syncthreads();

        uint32_t buf = sbase + (ch & 1) * BUF;
        uint32_t tA0 = buf, tW0 = buf + A_TILE;

        #pragma unroll
        for (int ks = 0; ks < 4; ks++) {
            int acol = ks*32 + a_colg;
            int bcol = ks*32 + b_colg;
            uint32_t aa[4][4];
            #pragma unroll
            for (int mf = 0; mf < 4; mf++) {
                uint32_t off = SWZ128((a_row + mf*16)*128 + acol);
                ldm_x4(aa[mf], tA0 + off);
            }
            #pragma unroll
            for (int q = 0; q < NFR/2; q++) {
                uint32_t off = SWZ128((b_row + q*16)*128 + bcol);
                uint32_t bb[4];
                ldm_x4(bb, tW0 + off);
                #pragma unroll
                for (int mf = 0; mf < 4; mf++)
                    #pragma unroll
                    for (int hlf = 0; hlf < 2; hlf++) {
                        int nf = q*2 + hlf;
                        mma_bf16(acc[mf][nf], aa[mf], &bb[hlf*2]);
                    }
            }
        }
        __syncthreads();
    }

    unsigned* sh = (unsigned*)dsm;
    for (int i = tid; i < 4096; i += 256) sh[i] = 0u;
    __syncthreads();

    const int b_base = (MODE ? n0 : m0) / L;
    const int tg = lane >> 2, tk = lane & 3;
    #pragma unroll
    for (int mf = 0; mf < 4; mf++) {
        #pragma unroll
        for (int h = 0; h < 2; h++) {
            int m = m0 + m_w + mf*16 + tg + h*8;
            if (m >= Mlim) continue;
            float smv = s2m[m];
            if (MODE == 0) {
                int b = m / L;
                int l = m - b*L;
                float* ob = out + ((size_t)b*NW)*L + l;
                int slot = (b - b_base) << 11;
                #pragma unroll
                for (int nf = 0; nf < NFR; nf++) {
                    #pragma unroll
                    for (int j = 0; j < 2; j++) {
                        int n = n0 + n_w + nf*8 + tk*2 + j;
                        if (n >= Nlim) continue;
                        float d2v = smv + s2n[n] - 2.0f * acc[mf][nf][h*2 + j];
                        float d = sqrtf(fmaxf(d2v, 0.0f));
                        ob[(size_t)n * L] = d;
                        atomicAdd(&sh[slot | (__float_as_uint(d) >> 21)], 1u);
                    }
                }
            } else {
                #pragma unroll
                for (int nf = 0; nf < NFR; nf++) {
                    #pragma unroll
                    for (int j = 0; j < 2; j++) {
                        int n = n0 + n_w + nf*8 + tk*2 + j;
                        if (n >= Nlim) continue;
                        int b = n / L;
                        int l = n - b*L;
                        float d2v = smv + s2n[n] - 2.0f * acc[mf][nf][h*2 + j];
                        float d = sqrtf(fmaxf(d2v, 0.0f));
                        out[((size_t)b*NW + m)*L + l] = d;
                        atomicAdd(&sh[((b - b_base) << 11) | (__float_as_uint(d) >> 21)], 1u);
                    }
                }
            }
        }
    }
    __syncthreads();
    for (int i = tid; i < 4096; i += 256) {
        unsigned v = sh[i];
        int bb = b_base + (i >> 11);
        if (v && bb < BATCH) atomicAdd(&h1[bb*2048 + (i & 2047)], v);
    }
}

// ---------------- fused triangle + FC: chunked partials ----------------
#define FC_CHUNK_LEN 4727
__global__ void __launch_bounds__(256) k_fcpart(const float* __restrict__ fcw,
                                                const float* __restrict__ w3) {
    int chunk = blockIdx.x, b = blockIdx.y;
    int k0 = chunk * FC_CHUNK_LEN;
    int k1 = k0 + FC_CHUNK_LEN; if (k1 > 75625) k1 = 75625;
    float thr = g_thrA[b];
    float invw = 1.0f / w3[0];
    const float4* src = (const float4*)(g_d3 + (size_t)b * 302500);
    float acc[10];
    #pragma unroll
    for (int n = 0; n < 10; n++) acc[n] = 0.f;
    for (int k = k0 + threadIdx.x; k < k1; k += 256) {
        float4 v = src[k];
        float t0 = (v.x > thr ? 0.f : 1.f - v.x*invw);
        float t1 = (v.y > thr ? 0.f : 1.f - v.y*invw);
        float t2 = (v.z > thr ? 0.f : 1.f - v.z*invw);
        float t3 = (v.w > thr ? 0.f : 1.f - v.w*invw);
        #pragma unroll
        for (int n = 0; n < 10; n++) {
            float4 w = ((const float4*)(fcw + (size_t)n * 302500))[k];
            acc[n] += t0*w.x + t1*w.y + t2*w.z + t3*w.w;
        }
    }
    __shared__ float red[256];
    #pragma unroll
    for (int n = 0; n < 10; n++) {
        red[threadIdx.x] = acc[n];
        __syncthreads();
        for (int st = 128; st > 0; st >>= 1) {
            if (threadIdx.x < st) red[threadIdx.x] += red[threadIdx.x + st];
            __syncthreads();
        }
        if (threadIdx.x == 0) g_fcpart[((size_t)chunk*BATCH + b)*10 + n] = red[0];
        __syncthreads();
    }
}

__global__ void k_fcfin(const float* __restrict__ fcb, float* __restrict__ out) {
    int i = threadIdx.x;
    if (i >= BATCH*10) return;
    int n = i % 10;
    float s = fcb[n];
    for (int c = 0; c < FC_CHUNKS; c++) s += g_fcpart[(size_t)c*BATCH*10 + i];
    out[i] = s;
}

// ---------------- host side ----------------
static void run_select(unsigned* h1, const float* data, int Nper, int kk,
                       const float* wptr, float* thrOut) {
    k_scan1p<<<BATCH, 256>>>(h1, kk);
    k_hist<<<dim3(64, BATCH), 256>>>(data, Nper, 10, 2048, 21);
    k_scanp<<<BATCH, 256>>>(2048, 10, 0, nullptr, nullptr);
    k_hist<<<dim3(64, BATCH), 256>>>(data, Nper, 0, 1024, 10);
    k_scanp<<<BATCH, 256>>>(1024, 0, 1, wptr, thrOut);
}

extern "C" void kernel_launch(void* const* d_in, const int* in_sizes, int n_in,
                              void* d_out, int out_size) {
    const float* x       = (const float*)d_in[0];
    const float* rgb_w   = (const float*)d_in[1];
    const float* gray_w  = (const float*)d_in[2];
    const float* conv1_w = (const float*)d_in[3];
    const float* conv2_w = (const float*)d_in[4];
    const float* fc_w    = (const float*)d_in[5];
    const float* fc_b    = (const float*)d_in[6];
    const float* w1      = (const float*)d_in[7];
    const float* w2      = (const float*)d_in[8];
    const float* w3      = (const float*)d_in[9];
    float* out = (float*)d_out;

    void *pd1, *pd1g, *pact2, *pact3, *pd2, *pd3, *pthrA, *pthrB;
    void *pc1h, *pc2h, *pw1h, *pw2h;
    void *ps2a, *ps2b, *pwsq1, *pwsq2, *ph1a, *ph1b;
    cudaGetSymbolAddress(&pd1,   g_d1);
    cudaGetSymbolAddress(&pd1g,  g_d1g);
    cudaGetSymbolAddress(&pact2, g_act2);
    cudaGetSymbolAddress(&pact3, g_act3);
    cudaGetSymbolAddress(&pd2,   g_d2);
    cudaGetSymbolAddress(&pd3,   g_d3);
    cudaGetSymbolAddress(&pthrA, g_thrA);
    cudaGetSymbolAddress(&pthrB, g_thrB);
    cudaGetSymbolAddress(&pc1h,  g_col1h);
    cudaGetSymbolAddress(&pc2h,  g_col2h);
    cudaGetSymbolAddress(&pw1h,  g_w1h);
    cudaGetSymbolAddress(&pw2h,  g_w2h);
    cudaGetSymbolAddress(&ps2a,  g_s2a);
    cudaGetSymbolAddress(&ps2b,  g_s2b);
    cudaGetSymbolAddress(&pwsq1, g_wsq1);
    cudaGetSymbolAddress(&pwsq2, g_wsq2);
    cudaGetSymbolAddress(&ph1a,  g_h1a);
    cudaGetSymbolAddress(&ph1b,  g_h1b);

    // conv1: BUF = 32K + 16K = 48K, x2 = 96K. conv2: BUF = 32K + 20K = 52K, x2 = 104K.
    cudaFuncSetAttribute((const void*)k_gemm_mma<1,8>,  cudaFuncAttributeMaxDynamicSharedMemorySize, 98304);
    cudaFuncSetAttribute((const void*)k_gemm_mma<0,10>, cudaFuncAttributeMaxDynamicSharedMemorySize, 106496);
    cudaFuncSetAttribute(k_im2col_stage, cudaFuncAttributeMaxDynamicSharedMemorySize, 81008);

    // stage 1
    k_gray<<<(BATCH*10000 + 255)/256, 256>>>(x);
    k_rgbconv<<<1152, 256>>>(x, rgb_w);
    k_grayconv<<<1152, 256>>>(gray_w);
    k_scan1m<<<64, 256>>>(345600, 115200);
    k_histm<<<dim3(64, 64), 256>>>((const float*)pd1, (const float*)pd1g, 10, 2048, 21);
    k_scanm<<<64, 256>>>(2048, 10, 0, w1);
    k_histm<<<dim3(64, 64), 256>>>((const float*)pd1, (const float*)pd1g, 0, 1024, 10);
    k_scanm<<<64, 256>>>(1024, 0, 1, w1);
    k_sfm1<<<(BATCH*230400 + 255)/256, 256>>>(w1);

    // conv1 (RBF, k=3, pad=1): (B,100,48,48) -> (B,225,48,48)
    k_im2col_stage<<<1536, 256, 63600>>>((const float*)pact2,
        (__nv_bfloat16*)pc1h, (float*)ps2a, 100, 48, 48, 48, 48, 1, 900, 960);
    k_wprep<<<(256*960 + 255)/256, 256>>>(conv1_w, (__nv_bfloat16*)pw1h, 225, 900, 256, 960);
    k_rowsq_h<<<(256*32 + 255)/256, 256>>>((const __nv_bfloat16*)pw1h, (float*)pwsq1, 256, 960);
    k_gemm_mma<1,8><<<dim3(576, 1), 256, 98304>>>(
        (const __nv_bfloat16*)pw1h, (const __nv_bfloat16*)pc1h,
        (const float*)pwsq1, (const float*)ps2a, (float*)pd2,
        960, 15, 225, 73728, 2304, 225, (unsigned*)ph1a);
    run_select((unsigned*)ph1a, (const float*)pd2, 518400, 207360, w2, (float*)pthrA);
    k_sfm2<<<(BATCH*129600 + 255)/256, 256>>>(w2);

    // conv2 (RBF, k=3, pad=0): (B,225,24,24) -> (B,625,22,22), N-tile 160 (244 CTAs = 2 waves)
    k_im2col_stage<<<704, 256, 81008>>>((const float*)pact3,
        (__nv_bfloat16*)pc2h, (float*)ps2b, 225, 24, 24, 22, 22, 0, 2025, 2048);
    k_wprep<<<(640*2048 + 255)/256, 256>>>(conv2_w, (__nv_bfloat16*)pw2h, 625, 2025, 640, 2048);
    k_rowsq_h<<<(640*32 + 255)/256, 256>>>((const __nv_bfloat16*)pw2h, (float*)pwsq2, 640, 2048);
    k_gemm_mma<0,10><<<dim3(4, 61), 256, 106496>>>(
        (const __nv_bfloat16*)pc2h, (const __nv_bfloat16*)pw2h,
        (const float*)ps2b, (const float*)pwsq2, (float*)pd3,
        2048, 32, 15488, 625, 484, 625, (unsigned*)ph1a);
    run_select((unsigned*)ph1a, (const float*)pd3, 302500, 121000, w3, (float*)pthrA);

    // fused triangle + FC
    k_fcpart<<<dim3(FC_CHUNKS, BATCH), 256>>>(fc_w, w3);
    k_fcfin<<<1, 320>>>(fc_b, out);
}